// round 9
// baseline (speedup 1.0000x reference)
#include <cuda_runtime.h>
#include <cstdint>
#include <cuda_fp16.h>
#include <mma.h>

using namespace nvcuda;

// Problem constants
#define BATCH 8
#define SEQ   2048
#define DIM   1024
#define MTOT  (BATCH * SEQ)        // 16384

// GEMM tiling: CTA 128x128 with 128 threads, warp 64x64, K-chunk 64, 2-stage
#define BM 128
#define BN 128
#define BK 64
#define NTHREADS 128
#define AKP 72                       // A row stride (halves) = 144 B
#define BKP 72                       // B trans row stride
#define BNP 136                      // B non-trans row stride = 272 B
#define A_STAGE 9216                 // 128*72 halves
#define B_STAGE 9216                 // max(128*72, 64*136) halves
#define STAGE_HALVES (A_STAGE + B_STAGE)
#define SMEM_BYTES (2 * STAGE_HALVES * 2)   // 73728 B

// Scratch (__device__ globals; allocation-free rule)
__device__ __half g_q[(long long)MTOT * DIM];        // 32 MB
__device__ __half g_k[(long long)MTOT * DIM];        // 32 MB
__device__ __half g_v[(long long)MTOT * DIM];        // 32 MB
__device__ float  g_s[(long long)BATCH * SEQ * SEQ]; // 128 MB (Xh/Wh, then half scores)

__device__ __forceinline__ void cp16(void* smem, const void* gmem) {
    unsigned s = (unsigned)__cvta_generic_to_shared(smem);
    asm volatile("cp.async.cg.shared.global [%0], [%1], 16;\n" :: "r"(s), "l"(gmem));
}
#define CP_COMMIT() asm volatile("cp.async.commit_group;\n")

// ---------------------------------------------------------------------------
// FP16 WMMA GEMM (fp32 accumulate), double-buffered cp.async.
//   4 warps per CTA, each owning a 64x64 output tile; 2 CTAs/SM.
//   C[M,N] = scale * (A[M,K] @ B(^T)) (+ bias, HALF_OUT only)
//   QKV3: blockIdx.z in {0,1,2} selects (B, bias, C); A shared across z.
// ---------------------------------------------------------------------------
template <bool TRANSB, bool HALF_OUT, bool QKV3>
__global__ __launch_bounds__(NTHREADS, 2)
void gemm_fp16(const __half* __restrict__ Ab, const __half* __restrict__ Bb,
               const float* __restrict__ bias, void* __restrict__ Cb,
               int K, int lda, int ldb, int ldc,
               long long sA, long long sB, long long sC, float scale,
               const __half* __restrict__ Bb1 = nullptr,
               const __half* __restrict__ Bb2 = nullptr,
               const float* __restrict__ bias1 = nullptr,
               const float* __restrict__ bias2 = nullptr,
               void* __restrict__ Cb1 = nullptr,
               void* __restrict__ Cb2 = nullptr)
{
    extern __shared__ __half sh[];
    __shared__ float epi[4][16 * 20];
    __shared__ float biasS[BN];

    const __half* A = Ab;
    const __half* B = Bb;
    const float*  bi = bias;
    void*         Cv = Cb;

    if constexpr (QKV3) {
        if (blockIdx.z == 1)      { B = Bb1; bi = bias1; Cv = Cb1; }
        else if (blockIdx.z == 2) { B = Bb2; bi = bias2; Cv = Cb2; }
    } else {
        A += (long long)blockIdx.z * sA;
        B += (long long)blockIdx.z * sB;
    }

    const int m0 = blockIdx.y * BM;
    const int n0 = blockIdx.x * BN;
    const int t  = threadIdx.x;
    const int warp = t >> 5;
    const int lid  = t & 31;
    const int wm = warp >> 1;   // 0..1 (64-row slab)
    const int wn = warp & 1;    // 0..1 (64-col slab)

    if (HALF_OUT) biasS[t] = bi ? bi[n0 + t] : 0.0f;

    wmma::fragment<wmma::accumulator, 16, 16, 16, float> acc[4][4];
    #pragma unroll
    for (int mi = 0; mi < 4; mi++)
        #pragma unroll
        for (int nj = 0; nj < 4; nj++)
            wmma::fill_fragment(acc[mi][nj], 0.0f);

    // Stage one K=64 chunk into buffer slot b (0/1)
    auto stage = [&](int chunk, int b) {
        const int k0 = chunk * BK;
        __half* Ad = sh + b * STAGE_HALVES;
        __half* Bd = Ad + A_STAGE;
        #pragma unroll
        for (int j = 0; j < 8; j++) {              // A: 128x64 = 1024 cp16
            int idx = t + NTHREADS * j;
            int r  = idx >> 3;                     // 0..127
            int c8 = (idx & 7) << 3;               // 0..56
            cp16(&Ad[r * AKP + c8], &A[(long long)(m0 + r) * lda + k0 + c8]);
        }
        if (TRANSB) {
            #pragma unroll
            for (int j = 0; j < 8; j++) {          // B: 128x64 = 1024 cp16
                int idx = t + NTHREADS * j;
                int r  = idx >> 3;
                int c8 = (idx & 7) << 3;
                cp16(&Bd[r * BKP + c8], &B[(long long)(n0 + r) * ldb + k0 + c8]);
            }
        } else {
            #pragma unroll
            for (int j = 0; j < 8; j++) {          // B: 64x128 = 1024 cp16
                int idx = t + NTHREADS * j;
                int r  = idx >> 4;                 // 0..63
                int c8 = (idx & 15) << 3;          // 0..120
                cp16(&Bd[r * BNP + c8], &B[(long long)(k0 + r) * ldb + n0 + c8]);
            }
        }
        CP_COMMIT();
    };

    const int nchunk = K / BK;
    stage(0, 0);

    int cur = 0;
    for (int i = 0; i < nchunk; i++) {
        if (i + 1 < nchunk) {
            stage(i + 1, cur ^ 1);
            asm volatile("cp.async.wait_group 1;\n");
        } else {
            asm volatile("cp.async.wait_group 0;\n");
        }
        __syncthreads();

        const __half* Ac = sh + cur * STAGE_HALVES;
        const __half* Bc = Ac + A_STAGE;

        #pragma unroll
        for (int kk = 0; kk < BK; kk += 16) {
            wmma::fragment<wmma::matrix_a, 16, 16, 16, __half, wmma::row_major> af[4];
            #pragma unroll
            for (int mi = 0; mi < 4; mi++)
                wmma::load_matrix_sync(af[mi], &Ac[(wm * 64 + mi * 16) * AKP + kk], AKP);

            #pragma unroll
            for (int nj = 0; nj < 4; nj++) {
                if constexpr (TRANSB) {
                    wmma::fragment<wmma::matrix_b, 16, 16, 16, __half,
                                   wmma::col_major> bf;
                    wmma::load_matrix_sync(bf, &Bc[(wn * 64 + nj * 16) * BKP + kk], BKP);
                    #pragma unroll
                    for (int mi = 0; mi < 4; mi++)
                        wmma::mma_sync(acc[mi][nj], af[mi], bf, acc[mi][nj]);
                } else {
                    wmma::fragment<wmma::matrix_b, 16, 16, 16, __half,
                                   wmma::row_major> bf;
                    wmma::load_matrix_sync(bf, &Bc[kk * BNP + wn * 64 + nj * 16], BNP);
                    #pragma unroll
                    for (int mi = 0; mi < 4; mi++)
                        wmma::mma_sync(acc[mi][nj], af[mi], bf, acc[mi][nj]);
                }
            }
        }
        __syncthreads();
        cur ^= 1;
    }

    // Epilogue
    if constexpr (!HALF_OUT) {
        float* C = (float*)Cv + (QKV3 ? 0LL : (long long)blockIdx.z * sC);
        #pragma unroll
        for (int mi = 0; mi < 4; mi++)
            #pragma unroll
            for (int nj = 0; nj < 4; nj++) {
                if (scale != 1.0f) {
                    #pragma unroll
                    for (int e = 0; e < acc[mi][nj].num_elements; e++)
                        acc[mi][nj].x[e] *= scale;
                }
                wmma::store_matrix_sync(
                    &C[(long long)(m0 + wm * 64 + mi * 16) * ldc + n0 + wn * 64 + nj * 16],
                    acc[mi][nj], ldc, wmma::mem_row_major);
            }
    } else {
        __half* C = (__half*)Cv + (QKV3 ? 0LL : (long long)blockIdx.z * sC);
        float* ep = epi[warp];
        const int r  = lid >> 1;          // 0..15
        const int ch = (lid & 1) * 8;     // 0 or 8
        #pragma unroll
        for (int mi = 0; mi < 4; mi++)
            #pragma unroll
            for (int nj = 0; nj < 4; nj++) {
                wmma::store_matrix_sync(ep, acc[mi][nj], 20, wmma::mem_row_major);
                __syncwarp();
                const int colb = wn * 64 + nj * 16 + ch;
                __half h[8];
                #pragma unroll
                for (int i = 0; i < 8; i++)
                    h[i] = __float2half_rn(ep[r * 20 + ch + i] * scale + biasS[colb + i]);
                *(uint4*)&C[(long long)(m0 + wm * 64 + mi * 16 + r) * ldc + n0 + colb] =
                    *(uint4*)h;
                __syncwarp();
            }
    }
}

// ---------------------------------------------------------------------------
// float -> half conversion (8 elems/thread, grid-stride)
// ---------------------------------------------------------------------------
__global__ __launch_bounds__(256)
void cvt_f2h(const float4* __restrict__ in, uint4* __restrict__ out, int n8)
{
    for (int i = blockIdx.x * blockDim.x + threadIdx.x; i < n8;
         i += gridDim.x * blockDim.x) {
        float4 a = in[i * 2], b = in[i * 2 + 1];
        __half h[8];
        h[0] = __float2half_rn(a.x); h[1] = __float2half_rn(a.y);
        h[2] = __float2half_rn(a.z); h[3] = __float2half_rn(a.w);
        h[4] = __float2half_rn(b.x); h[5] = __float2half_rn(b.y);
        h[6] = __float2half_rn(b.z); h[7] = __float2half_rn(b.w);
        out[i] = *(uint4*)h;
    }
}

// ---------------------------------------------------------------------------
// Row softmax over 2048 HALF scores, fp32 math, writes half in place.
// ---------------------------------------------------------------------------
__global__ __launch_bounds__(256)
void softmax2048h(__half* __restrict__ S)
{
    __half* p = S + (long long)blockIdx.x * SEQ;
    const int t = threadIdx.x;

    uint4 raw = *(const uint4*)&p[t * 8];
    __half* hp = (__half*)&raw;
    float x[8];
    #pragma unroll
    for (int i = 0; i < 8; i++) x[i] = __half2float(hp[i]);

    float m = x[0];
    #pragma unroll
    for (int i = 1; i < 8; i++) m = fmaxf(m, x[i]);
    #pragma unroll
    for (int o = 16; o > 0; o >>= 1)
        m = fmaxf(m, __shfl_xor_sync(0xffffffffu, m, o));

    __shared__ float sm[8], ss[8];
    if ((t & 31) == 0) sm[t >> 5] = m;
    __syncthreads();
    m = fmaxf(fmaxf(fmaxf(sm[0], sm[1]), fmaxf(sm[2], sm[3])),
              fmaxf(fmaxf(sm[4], sm[5]), fmaxf(sm[6], sm[7])));

    float s = 0.0f;
    #pragma unroll
    for (int i = 0; i < 8; i++) { x[i] = __expf(x[i] - m); s += x[i]; }
    #pragma unroll
    for (int o = 16; o > 0; o >>= 1)
        s += __shfl_xor_sync(0xffffffffu, s, o);
    if ((t & 31) == 0) ss[t >> 5] = s;
    __syncthreads();
    s = (ss[0] + ss[1] + ss[2] + ss[3]) + (ss[4] + ss[5] + ss[6] + ss[7]);

    float inv = 1.0f / s;
    #pragma unroll
    for (int i = 0; i < 8; i++) hp[i] = __float2half_rn(x[i] * inv);
    *(uint4*)&p[t * 8] = raw;
}

// ---------------------------------------------------------------------------
extern "C" void kernel_launch(void* const* d_in, const int* in_sizes, int n_in,
                              void* d_out, int out_size)
{
    const float* X  = (const float*)d_in[0];
    const float* Wq = (const float*)d_in[1];
    const float* bq = (const float*)d_in[2];
    const float* Wk = (const float*)d_in[3];
    const float* bk = (const float*)d_in[4];
    const float* Wv = (const float*)d_in[5];
    const float* bv = (const float*)d_in[6];
    float* out = (float*)d_out;

    __half *q, *k, *v;
    float* s;
    cudaGetSymbolAddress((void**)&q, g_q);
    cudaGetSymbolAddress((void**)&k, g_k);
    cudaGetSymbolAddress((void**)&v, g_v);
    cudaGetSymbolAddress((void**)&s, g_s);

    cudaFuncSetAttribute(gemm_fp16<false, true, true>,
                         cudaFuncAttributeMaxDynamicSharedMemorySize, SMEM_BYTES);
    cudaFuncSetAttribute(gemm_fp16<true, true, false>,
                         cudaFuncAttributeMaxDynamicSharedMemorySize, SMEM_BYTES);
    cudaFuncSetAttribute(gemm_fp16<false, false, false>,
                         cudaFuncAttributeMaxDynamicSharedMemorySize, SMEM_BYTES);

    const long long TD = (long long)SEQ * DIM;   // 2097152
    const long long TT = (long long)SEQ * SEQ;   // 4194304

    // Half scratch inside g_s until phase 2 overwrites it with half scores:
    __half* Xh  = (__half*)s;                                  // 16M halves
    __half* Wqh = (__half*)(s + (long long)MTOT * DIM / 2);
    __half* Wkh = Wqh + (long long)DIM * DIM;
    __half* Wvh = Wkh + (long long)DIM * DIM;
    __half* Sh  = (__half*)s;                                  // scores/P (64 MB)

    // Phase 0: convert inputs to half
    cvt_f2h<<<2048, 256>>>((const float4*)X,  (uint4*)Xh,  MTOT * DIM / 8);
    cvt_f2h<<<512, 256>>>((const float4*)Wq, (uint4*)Wqh, DIM * DIM / 8);
    cvt_f2h<<<512, 256>>>((const float4*)Wk, (uint4*)Wkh, DIM * DIM / 8);
    cvt_f2h<<<512, 256>>>((const float4*)Wv, (uint4*)Wvh, DIM * DIM / 8);

    // Phase 1: fused Q/K/V projections (z selects W/bias/out)
    {
        dim3 grid(DIM / BN, MTOT / BM, 3);  // (8, 128, 3)
        gemm_fp16<false, true, true><<<grid, NTHREADS, SMEM_BYTES>>>(
            Xh, Wqh, bq, q, DIM, DIM, DIM, DIM, 0, 0, 0, 1.0f,
            Wkh, Wvh, bk, bv, k, v);
    }

    // Phase 2: scores = (Q @ K^T) / 32, written as HALF
    {
        dim3 grid(SEQ / BN, SEQ / BM, BATCH);  // (16, 16, 8)
        gemm_fp16<true, true, false><<<grid, NTHREADS, SMEM_BYTES>>>(
            q, k, nullptr, Sh, DIM, DIM, DIM, SEQ, TD, TD, TT, 0.03125f);
    }

    // Phase 3: softmax on half scores, in place
    softmax2048h<<<MTOT, 256>>>(Sh);

    // Phase 4: out = P @ V (A = half P, contiguous lda = SEQ)
    {
        dim3 grid(DIM / BN, SEQ / BM, BATCH);  // (8, 16, 8)
        gemm_fp16<false, false, false><<<grid, NTHREADS, SMEM_BYTES>>>(
            Sh, v, nullptr, out, SEQ, SEQ, DIM, DIM, TT, TD, TD, 1.0f);
    }
}

// round 10
// speedup vs baseline: 1.4792x; 1.4792x over previous
#include <cuda_runtime.h>
#include <cstdint>
#include <cuda_fp16.h>
#include <mma.h>

using namespace nvcuda;

// Problem constants
#define BATCH 8
#define SEQ   2048
#define DIM   1024
#define MTOT  (BATCH * SEQ)        // 16384

// GEMM tiling: CTA 128x128, warp 64x32, K-chunk 64, 3-stage single-sync
#define BM 128
#define BN 128
#define BK 64
#define AKP 72                       // A row stride (halves) = 144 B
#define BKP 72                       // B trans row stride
#define BNP 136                      // B non-trans row stride = 272 B
#define A_STAGE 9216                 // 128*72 halves
#define B_STAGE 9216                 // max(128*72, 64*136) halves
#define STAGE_HALVES (A_STAGE + B_STAGE)
#define NSTAGE 3
#define SMEM_BYTES (NSTAGE * STAGE_HALVES * 2)   // 110592 B (2 CTAs = 216KB/SM)

// Scratch (__device__ globals; allocation-free rule)
__device__ __half g_q[(long long)MTOT * DIM];        // 32 MB
__device__ __half g_k[(long long)MTOT * DIM];        // 32 MB
__device__ __half g_v[(long long)MTOT * DIM];        // 32 MB
__device__ float  g_s[(long long)BATCH * SEQ * SEQ]; // 128 MB (Xh/Wh, then half scores)

__device__ __forceinline__ void cp16(void* smem, const void* gmem) {
    unsigned s = (unsigned)__cvta_generic_to_shared(smem);
    asm volatile("cp.async.cg.shared.global [%0], [%1], 16;\n" :: "r"(s), "l"(gmem));
}
#define CP_COMMIT() asm volatile("cp.async.commit_group;\n")

// ---------------------------------------------------------------------------
// FP16 WMMA GEMM (fp32 accumulate), 3-stage cp.async, ONE barrier per chunk.
//   C[M,N] = scale * (A[M,K] @ B(^T)) (+ bias, HALF_OUT only)
//   QKV3: blockIdx.z in {0,1,2} selects (B, bias, C); A shared across z.
// Safety of single sync: stage(i+2) is issued after the barrier of iteration i;
// it writes buffer (i+2)%3 == (i-1)%3, whose compute finished before that
// barrier in every warp. wait_group(1) guarantees chunk i's data has landed.
// ---------------------------------------------------------------------------
template <bool TRANSB, bool HALF_OUT, bool QKV3>
__global__ __launch_bounds__(256, 2)
void gemm_fp16(const __half* __restrict__ Ab, const __half* __restrict__ Bb,
               const float* __restrict__ bias, void* __restrict__ Cb,
               int K, int lda, int ldb, int ldc,
               long long sA, long long sB, long long sC, float scale,
               const __half* __restrict__ Bb1 = nullptr,
               const __half* __restrict__ Bb2 = nullptr,
               const float* __restrict__ bias1 = nullptr,
               const float* __restrict__ bias2 = nullptr,
               void* __restrict__ Cb1 = nullptr,
               void* __restrict__ Cb2 = nullptr)
{
    extern __shared__ __half sh[];
    __shared__ float epi[8][16 * 20];
    __shared__ float biasS[BN];

    const __half* A = Ab;
    const __half* B = Bb;
    const float*  bi = bias;
    void*         Cv = Cb;

    if constexpr (QKV3) {
        if (blockIdx.z == 1)      { B = Bb1; bi = bias1; Cv = Cb1; }
        else if (blockIdx.z == 2) { B = Bb2; bi = bias2; Cv = Cb2; }
    } else {
        A += (long long)blockIdx.z * sA;
        B += (long long)blockIdx.z * sB;
    }

    const int m0 = blockIdx.y * BM;
    const int n0 = blockIdx.x * BN;
    const int t  = threadIdx.x;
    const int warp = t >> 5;
    const int lid  = t & 31;
    const int wm = warp >> 2;   // 0..1 (64-row slab)
    const int wn = warp & 3;    // 0..3 (32-col slab)

    if (HALF_OUT && t < BN) biasS[t] = bi ? bi[n0 + t] : 0.0f;

    wmma::fragment<wmma::accumulator, 16, 16, 16, float> acc[4][2];
    #pragma unroll
    for (int mi = 0; mi < 4; mi++)
        #pragma unroll
        for (int nj = 0; nj < 2; nj++)
            wmma::fill_fragment(acc[mi][nj], 0.0f);

    // Stage one K=64 chunk into stage slot st (0..2)
    auto stage = [&](int chunk, int st) {
        const int k0 = chunk * BK;
        __half* Ad = sh + st * STAGE_HALVES;
        __half* Bd = Ad + A_STAGE;
        #pragma unroll
        for (int j = 0; j < 4; j++) {              // A: 128x64 = 1024 cp16
            int idx = t + 256 * j;
            int r  = idx >> 3;                     // 0..127
            int c8 = (idx & 7) << 3;               // 0..56
            cp16(&Ad[r * AKP + c8], &A[(long long)(m0 + r) * lda + k0 + c8]);
        }
        if (TRANSB) {
            #pragma unroll
            for (int j = 0; j < 4; j++) {          // B: 128x64 = 1024 cp16
                int idx = t + 256 * j;
                int r  = idx >> 3;
                int c8 = (idx & 7) << 3;
                cp16(&Bd[r * BKP + c8], &B[(long long)(n0 + r) * ldb + k0 + c8]);
            }
        } else {
            #pragma unroll
            for (int j = 0; j < 4; j++) {          // B: 64x128 = 1024 cp16
                int idx = t + 256 * j;
                int r  = idx >> 4;                 // 0..63
                int c8 = (idx & 15) << 3;          // 0..120
                cp16(&Bd[r * BNP + c8], &B[(long long)(k0 + r) * ldb + n0 + c8]);
            }
        }
        CP_COMMIT();
    };

    const int nchunk = K / BK;
    stage(0, 0);
    if (nchunk > 1) stage(1, 1);

    int st = 0;
    for (int i = 0; i < nchunk; i++) {
        if (i + 1 < nchunk) asm volatile("cp.async.wait_group 1;\n");
        else                asm volatile("cp.async.wait_group 0;\n");
        __syncthreads();

        if (i + 2 < nchunk) {
            int ns = st + 2; if (ns >= NSTAGE) ns -= NSTAGE;
            stage(i + 2, ns);
        }

        const __half* Ac = sh + st * STAGE_HALVES;
        const __half* Bc = Ac + A_STAGE;

        #pragma unroll
        for (int kk = 0; kk < BK; kk += 16) {
            wmma::fragment<wmma::matrix_a, 16, 16, 16, __half, wmma::row_major> af[4];
            #pragma unroll
            for (int mi = 0; mi < 4; mi++)
                wmma::load_matrix_sync(af[mi], &Ac[(wm * 64 + mi * 16) * AKP + kk], AKP);

            #pragma unroll
            for (int nj = 0; nj < 2; nj++) {
                if constexpr (TRANSB) {
                    wmma::fragment<wmma::matrix_b, 16, 16, 16, __half,
                                   wmma::col_major> bf;
                    wmma::load_matrix_sync(bf, &Bc[(wn * 32 + nj * 16) * BKP + kk], BKP);
                    #pragma unroll
                    for (int mi = 0; mi < 4; mi++)
                        wmma::mma_sync(acc[mi][nj], af[mi], bf, acc[mi][nj]);
                } else {
                    wmma::fragment<wmma::matrix_b, 16, 16, 16, __half,
                                   wmma::row_major> bf;
                    wmma::load_matrix_sync(bf, &Bc[kk * BNP + wn * 32 + nj * 16], BNP);
                    #pragma unroll
                    for (int mi = 0; mi < 4; mi++)
                        wmma::mma_sync(acc[mi][nj], af[mi], bf, acc[mi][nj]);
                }
            }
        }
        st += 1; if (st >= NSTAGE) st -= NSTAGE;
    }

    // Epilogue
    if constexpr (!HALF_OUT) {
        float* C = (float*)Cv + (QKV3 ? 0LL : (long long)blockIdx.z * sC);
        #pragma unroll
        for (int mi = 0; mi < 4; mi++)
            #pragma unroll
            for (int nj = 0; nj < 2; nj++) {
                if (scale != 1.0f) {
                    #pragma unroll
                    for (int e = 0; e < acc[mi][nj].num_elements; e++)
                        acc[mi][nj].x[e] *= scale;
                }
                wmma::store_matrix_sync(
                    &C[(long long)(m0 + wm * 64 + mi * 16) * ldc + n0 + wn * 32 + nj * 16],
                    acc[mi][nj], ldc, wmma::mem_row_major);
            }
    } else {
        __half* C = (__half*)Cv + (QKV3 ? 0LL : (long long)blockIdx.z * sC);
        float* ep = epi[warp];
        const int r  = lid >> 1;          // 0..15
        const int ch = (lid & 1) * 8;     // 0 or 8
        #pragma unroll
        for (int mi = 0; mi < 4; mi++)
            #pragma unroll
            for (int nj = 0; nj < 2; nj++) {
                wmma::store_matrix_sync(ep, acc[mi][nj], 20, wmma::mem_row_major);
                __syncwarp();
                const int colb = wn * 32 + nj * 16 + ch;
                __half h[8];
                #pragma unroll
                for (int i = 0; i < 8; i++)
                    h[i] = __float2half_rn(ep[r * 20 + ch + i] * scale + biasS[colb + i]);
                *(uint4*)&C[(long long)(m0 + wm * 64 + mi * 16 + r) * ldc + n0 + colb] =
                    *(uint4*)h;
                __syncwarp();
            }
    }
}

// ---------------------------------------------------------------------------
// float -> half conversion (8 elems/thread, grid-stride)
// ---------------------------------------------------------------------------
__global__ __launch_bounds__(256)
void cvt_f2h(const float4* __restrict__ in, uint4* __restrict__ out, int n8)
{
    for (int i = blockIdx.x * blockDim.x + threadIdx.x; i < n8;
         i += gridDim.x * blockDim.x) {
        float4 a = in[i * 2], b = in[i * 2 + 1];
        __half h[8];
        h[0] = __float2half_rn(a.x); h[1] = __float2half_rn(a.y);
        h[2] = __float2half_rn(a.z); h[3] = __float2half_rn(a.w);
        h[4] = __float2half_rn(b.x); h[5] = __float2half_rn(b.y);
        h[6] = __float2half_rn(b.z); h[7] = __float2half_rn(b.w);
        out[i] = *(uint4*)h;
    }
}

// ---------------------------------------------------------------------------
// Row softmax over 2048 HALF scores, fp32 math, writes half in place.
// ---------------------------------------------------------------------------
__global__ __launch_bounds__(256)
void softmax2048h(__half* __restrict__ S)
{
    __half* p = S + (long long)blockIdx.x * SEQ;
    const int t = threadIdx.x;

    uint4 raw = *(const uint4*)&p[t * 8];
    __half* hp = (__half*)&raw;
    float x[8];
    #pragma unroll
    for (int i = 0; i < 8; i++) x[i] = __half2float(hp[i]);

    float m = x[0];
    #pragma unroll
    for (int i = 1; i < 8; i++) m = fmaxf(m, x[i]);
    #pragma unroll
    for (int o = 16; o > 0; o >>= 1)
        m = fmaxf(m, __shfl_xor_sync(0xffffffffu, m, o));

    __shared__ float sm[8], ss[8];
    if ((t & 31) == 0) sm[t >> 5] = m;
    __syncthreads();
    m = fmaxf(fmaxf(fmaxf(sm[0], sm[1]), fmaxf(sm[2], sm[3])),
              fmaxf(fmaxf(sm[4], sm[5]), fmaxf(sm[6], sm[7])));

    float s = 0.0f;
    #pragma unroll
    for (int i = 0; i < 8; i++) { x[i] = __expf(x[i] - m); s += x[i]; }
    #pragma unroll
    for (int o = 16; o > 0; o >>= 1)
        s += __shfl_xor_sync(0xffffffffu, s, o);
    if ((t & 31) == 0) ss[t >> 5] = s;
    __syncthreads();
    s = (ss[0] + ss[1] + ss[2] + ss[3]) + (ss[4] + ss[5] + ss[6] + ss[7]);

    float inv = 1.0f / s;
    #pragma unroll
    for (int i = 0; i < 8; i++) hp[i] = __float2half_rn(x[i] * inv);
    *(uint4*)&p[t * 8] = raw;
}

// ---------------------------------------------------------------------------
extern "C" void kernel_launch(void* const* d_in, const int* in_sizes, int n_in,
                              void* d_out, int out_size)
{
    const float* X  = (const float*)d_in[0];
    const float* Wq = (const float*)d_in[1];
    const float* bq = (const float*)d_in[2];
    const float* Wk = (const float*)d_in[3];
    const float* bk = (const float*)d_in[4];
    const float* Wv = (const float*)d_in[5];
    const float* bv = (const float*)d_in[6];
    float* out = (float*)d_out;

    __half *q, *k, *v;
    float* s;
    cudaGetSymbolAddress((void**)&q, g_q);
    cudaGetSymbolAddress((void**)&k, g_k);
    cudaGetSymbolAddress((void**)&v, g_v);
    cudaGetSymbolAddress((void**)&s, g_s);

    cudaFuncSetAttribute(gemm_fp16<false, true, true>,
                         cudaFuncAttributeMaxDynamicSharedMemorySize, SMEM_BYTES);
    cudaFuncSetAttribute(gemm_fp16<true, true, false>,
                         cudaFuncAttributeMaxDynamicSharedMemorySize, SMEM_BYTES);
    cudaFuncSetAttribute(gemm_fp16<false, false, false>,
                         cudaFuncAttributeMaxDynamicSharedMemorySize, SMEM_BYTES);

    const long long TD = (long long)SEQ * DIM;   // 2097152
    const long long TT = (long long)SEQ * SEQ;   // 4194304

    // Half scratch inside g_s until phase 2 overwrites it with half scores:
    __half* Xh  = (__half*)s;                                  // 16M halves
    __half* Wqh = (__half*)(s + (long long)MTOT * DIM / 2);
    __half* Wkh = Wqh + (long long)DIM * DIM;
    __half* Wvh = Wkh + (long long)DIM * DIM;
    __half* Sh  = (__half*)s;                                  // scores/P (64 MB)

    // Phase 0: convert inputs to half
    cvt_f2h<<<2048, 256>>>((const float4*)X,  (uint4*)Xh,  MTOT * DIM / 8);
    cvt_f2h<<<512, 256>>>((const float4*)Wq, (uint4*)Wqh, DIM * DIM / 8);
    cvt_f2h<<<512, 256>>>((const float4*)Wk, (uint4*)Wkh, DIM * DIM / 8);
    cvt_f2h<<<512, 256>>>((const float4*)Wv, (uint4*)Wvh, DIM * DIM / 8);

    // Phase 1: fused Q/K/V projections (z selects W/bias/out)
    {
        dim3 grid(DIM / BN, MTOT / BM, 3);  // (8, 128, 3)
        gemm_fp16<false, true, true><<<grid, 256, SMEM_BYTES>>>(
            Xh, Wqh, bq, q, DIM, DIM, DIM, DIM, 0, 0, 0, 1.0f,
            Wkh, Wvh, bk, bv, k, v);
    }

    // Phase 2: scores = (Q @ K^T) / 32, written as HALF
    {
        dim3 grid(SEQ / BN, SEQ / BM, BATCH);  // (16, 16, 8)
        gemm_fp16<true, true, false><<<grid, 256, SMEM_BYTES>>>(
            q, k, nullptr, Sh, DIM, DIM, DIM, SEQ, TD, TD, TT, 0.03125f);
    }

    // Phase 3: softmax on half scores, in place
    softmax2048h<<<MTOT, 256>>>(Sh);

    // Phase 4: out = P @ V (A = half P, contiguous lda = SEQ)
    {
        dim3 grid(DIM / BN, SEQ / BM, BATCH);  // (8, 16, 8)
        gemm_fp16<false, false, false><<<grid, 256, SMEM_BYTES>>>(
            Sh, v, nullptr, out, SEQ, SEQ, DIM, DIM, TT, TD, TD, 1.0f);
    }
}

// round 11
// speedup vs baseline: 1.7354x; 1.1732x over previous
#include <cuda_runtime.h>
#include <cstdint>
#include <cuda_fp16.h>
#include <mma.h>

using namespace nvcuda;

// Problem constants
#define BATCH 8
#define SEQ   2048
#define DIM   1024
#define MTOT  (BATCH * SEQ)        // 16384

// GEMM tiling: CTA 128x128, warp 64x32, K-chunk 64, double-buffered cp.async
#define BM 128
#define BN 128
#define BK 64
#define AKP 72                       // A row stride (halves) = 144 B
#define BKP 72                       // B trans row stride
#define BNP 136                      // B non-trans row stride = 272 B
#define A_STAGE 9216                 // 128*72 halves
#define B_STAGE 9216                 // max(128*72, 64*136) halves
#define STAGE_HALVES (A_STAGE + B_STAGE)
#define SMEM_BYTES (2 * STAGE_HALVES * 2)   // 73728 B (2 CTAs/SM = 144KB)

// Scratch (__device__ globals; allocation-free rule)
__device__ __half g_q[(long long)MTOT * DIM];        // 32 MB
__device__ __half g_k[(long long)MTOT * DIM];        // 32 MB
__device__ __half g_v[(long long)MTOT * DIM];        // 32 MB
__device__ float  g_s[(long long)BATCH * SEQ * SEQ]; // 128 MB (Xh/Wh, then half scores)

__device__ __forceinline__ void cp16(void* smem, const void* gmem) {
    unsigned s = (unsigned)__cvta_generic_to_shared(smem);
    asm volatile("cp.async.cg.shared.global [%0], [%1], 16;\n" :: "r"(s), "l"(gmem));
}
#define CP_COMMIT() asm volatile("cp.async.commit_group;\n")

// ---------------------------------------------------------------------------
// FP16 WMMA GEMM (fp32 accumulate), double-buffered cp.async, 64x32 warp tiles.
//   C[M,N] = scale * (A[M,K] @ B(^T)) (+ bias, HALF_OUT only)
//   QKV3: blockIdx.z in {0,1,2} selects (B, bias, C); A shared across z.
// ---------------------------------------------------------------------------
template <bool TRANSB, bool HALF_OUT, bool QKV3>
__global__ __launch_bounds__(256, 2)
void gemm_fp16(const __half* __restrict__ Ab, const __half* __restrict__ Bb,
               const float* __restrict__ bias, void* __restrict__ Cb,
               int K, int lda, int ldb, int ldc,
               long long sA, long long sB, long long sC, float scale,
               const __half* __restrict__ Bb1 = nullptr,
               const __half* __restrict__ Bb2 = nullptr,
               const float* __restrict__ bias1 = nullptr,
               const float* __restrict__ bias2 = nullptr,
               void* __restrict__ Cb1 = nullptr,
               void* __restrict__ Cb2 = nullptr)
{
    extern __shared__ __half sh[];
    __shared__ float epi[8][16 * 20];
    __shared__ float biasS[BN];

    const __half* A = Ab;
    const __half* B = Bb;
    const float*  bi = bias;
    void*         Cv = Cb;

    if constexpr (QKV3) {
        if (blockIdx.z == 1)      { B = Bb1; bi = bias1; Cv = Cb1; }
        else if (blockIdx.z == 2) { B = Bb2; bi = bias2; Cv = Cb2; }
    } else {
        A += (long long)blockIdx.z * sA;
        B += (long long)blockIdx.z * sB;
    }

    const int m0 = blockIdx.y * BM;
    const int n0 = blockIdx.x * BN;
    const int t  = threadIdx.x;
    const int warp = t >> 5;
    const int lid  = t & 31;
    const int wm = warp >> 2;   // 0..1 (64-row slab)
    const int wn = warp & 3;    // 0..3 (32-col slab)

    if (HALF_OUT && t < BN) biasS[t] = bi ? bi[n0 + t] : 0.0f;

    wmma::fragment<wmma::accumulator, 16, 16, 16, float> acc[4][2];
    #pragma unroll
    for (int mi = 0; mi < 4; mi++)
        #pragma unroll
        for (int nj = 0; nj < 2; nj++)
            wmma::fill_fragment(acc[mi][nj], 0.0f);

    // Stage one K=64 chunk into buffer slot b (0/1)
    auto stage = [&](int chunk, int b) {
        const int k0 = chunk * BK;
        __half* Ad = sh + b * STAGE_HALVES;
        __half* Bd = Ad + A_STAGE;
        #pragma unroll
        for (int j = 0; j < 4; j++) {              // A: 128x64 = 1024 cp16
            int idx = t + 256 * j;
            int r  = idx >> 3;                     // 0..127
            int c8 = (idx & 7) << 3;               // 0..56
            cp16(&Ad[r * AKP + c8], &A[(long long)(m0 + r) * lda + k0 + c8]);
        }
        if (TRANSB) {
            #pragma unroll
            for (int j = 0; j < 4; j++) {          // B: 128x64 = 1024 cp16
                int idx = t + 256 * j;
                int r  = idx >> 3;
                int c8 = (idx & 7) << 3;
                cp16(&Bd[r * BKP + c8], &B[(long long)(n0 + r) * ldb + k0 + c8]);
            }
        } else {
            #pragma unroll
            for (int j = 0; j < 4; j++) {          // B: 64x128 = 1024 cp16
                int idx = t + 256 * j;
                int r  = idx >> 4;                 // 0..63
                int c8 = (idx & 15) << 3;          // 0..120
                cp16(&Bd[r * BNP + c8], &B[(long long)(k0 + r) * ldb + n0 + c8]);
            }
        }
        CP_COMMIT();
    };

    const int nchunk = K / BK;
    stage(0, 0);

    int cur = 0;
    for (int i = 0; i < nchunk; i++) {
        if (i + 1 < nchunk) {
            stage(i + 1, cur ^ 1);
            asm volatile("cp.async.wait_group 1;\n");
        } else {
            asm volatile("cp.async.wait_group 0;\n");
        }
        __syncthreads();

        const __half* Ac = sh + cur * STAGE_HALVES;
        const __half* Bc = Ac + A_STAGE;

        #pragma unroll
        for (int kk = 0; kk < BK; kk += 16) {
            wmma::fragment<wmma::matrix_a, 16, 16, 16, __half, wmma::row_major> af[4];
            #pragma unroll
            for (int mi = 0; mi < 4; mi++)
                wmma::load_matrix_sync(af[mi], &Ac[(wm * 64 + mi * 16) * AKP + kk], AKP);

            #pragma unroll
            for (int nj = 0; nj < 2; nj++) {
                if constexpr (TRANSB) {
                    wmma::fragment<wmma::matrix_b, 16, 16, 16, __half,
                                   wmma::col_major> bf;
                    wmma::load_matrix_sync(bf, &Bc[(wn * 32 + nj * 16) * BKP + kk], BKP);
                    #pragma unroll
                    for (int mi = 0; mi < 4; mi++)
                        wmma::mma_sync(acc[mi][nj], af[mi], bf, acc[mi][nj]);
                } else {
                    wmma::fragment<wmma::matrix_b, 16, 16, 16, __half,
                                   wmma::row_major> bf;
                    wmma::load_matrix_sync(bf, &Bc[kk * BNP + wn * 32 + nj * 16], BNP);
                    #pragma unroll
                    for (int mi = 0; mi < 4; mi++)
                        wmma::mma_sync(acc[mi][nj], af[mi], bf, acc[mi][nj]);
                }
            }
        }
        __syncthreads();
        cur ^= 1;
    }

    // Epilogue
    if constexpr (!HALF_OUT) {
        float* C = (float*)Cv + (QKV3 ? 0LL : (long long)blockIdx.z * sC);
        #pragma unroll
        for (int mi = 0; mi < 4; mi++)
            #pragma unroll
            for (int nj = 0; nj < 2; nj++) {
                if (scale != 1.0f) {
                    #pragma unroll
                    for (int e = 0; e < acc[mi][nj].num_elements; e++)
                        acc[mi][nj].x[e] *= scale;
                }
                wmma::store_matrix_sync(
                    &C[(long long)(m0 + wm * 64 + mi * 16) * ldc + n0 + wn * 32 + nj * 16],
                    acc[mi][nj], ldc, wmma::mem_row_major);
            }
    } else {
        __half* C = (__half*)Cv + (QKV3 ? 0LL : (long long)blockIdx.z * sC);
        float* ep = epi[warp];
        const int r  = lid >> 1;          // 0..15
        const int ch = (lid & 1) * 8;     // 0 or 8
        #pragma unroll
        for (int mi = 0; mi < 4; mi++)
            #pragma unroll
            for (int nj = 0; nj < 2; nj++) {
                wmma::store_matrix_sync(ep, acc[mi][nj], 20, wmma::mem_row_major);
                __syncwarp();
                const int colb = wn * 32 + nj * 16 + ch;
                __half h[8];
                #pragma unroll
                for (int i = 0; i < 8; i++)
                    h[i] = __float2half_rn(ep[r * 20 + ch + i] * scale + biasS[colb + i]);
                *(uint4*)&C[(long long)(m0 + wm * 64 + mi * 16 + r) * ldc + n0 + colb] =
                    *(uint4*)h;
                __syncwarp();
            }
    }
}

// ---------------------------------------------------------------------------
// Fused float->half conversion of X, Wq, Wk, Wv in ONE launch.
// Segment 0: X (MTOT*DIM elems); segments 1..3: W (DIM*DIM each).
// ---------------------------------------------------------------------------
__global__ __launch_bounds__(256)
void cvt_f2h_all(const float4* __restrict__ X,  uint4* __restrict__ Xo,
                 const float4* __restrict__ W0, uint4* __restrict__ W0o,
                 const float4* __restrict__ W1, uint4* __restrict__ W1o,
                 const float4* __restrict__ W2, uint4* __restrict__ W2o)
{
    const int NX = MTOT * DIM / 8;     // 2097152
    const int NW = DIM * DIM / 8;      // 131072
    const int total = NX + 3 * NW;
    for (int i = blockIdx.x * blockDim.x + threadIdx.x; i < total;
         i += gridDim.x * blockDim.x) {
        const float4* in; uint4* out; int j;
        if (i < NX)                { in = X;  out = Xo;  j = i; }
        else if (i < NX + NW)      { in = W0; out = W0o; j = i - NX; }
        else if (i < NX + 2 * NW)  { in = W1; out = W1o; j = i - NX - NW; }
        else                       { in = W2; out = W2o; j = i - NX - 2 * NW; }
        float4 a = in[j * 2], b = in[j * 2 + 1];
        __half h[8];
        h[0] = __float2half_rn(a.x); h[1] = __float2half_rn(a.y);
        h[2] = __float2half_rn(a.z); h[3] = __float2half_rn(a.w);
        h[4] = __float2half_rn(b.x); h[5] = __float2half_rn(b.y);
        h[6] = __float2half_rn(b.z); h[7] = __float2half_rn(b.w);
        out[j] = *(uint4*)h;
    }
}

// ---------------------------------------------------------------------------
// Row softmax over 2048 HALF scores, fp32 math, writes half in place.
// ---------------------------------------------------------------------------
__global__ __launch_bounds__(256)
void softmax2048h(__half* __restrict__ S)
{
    __half* p = S + (long long)blockIdx.x * SEQ;
    const int t = threadIdx.x;

    uint4 raw = *(const uint4*)&p[t * 8];
    __half* hp = (__half*)&raw;
    float x[8];
    #pragma unroll
    for (int i = 0; i < 8; i++) x[i] = __half2float(hp[i]);

    float m = x[0];
    #pragma unroll
    for (int i = 1; i < 8; i++) m = fmaxf(m, x[i]);
    #pragma unroll
    for (int o = 16; o > 0; o >>= 1)
        m = fmaxf(m, __shfl_xor_sync(0xffffffffu, m, o));

    __shared__ float sm[8], ss[8];
    if ((t & 31) == 0) sm[t >> 5] = m;
    __syncthreads();
    m = fmaxf(fmaxf(fmaxf(sm[0], sm[1]), fmaxf(sm[2], sm[3])),
              fmaxf(fmaxf(sm[4], sm[5]), fmaxf(sm[6], sm[7])));

    float s = 0.0f;
    #pragma unroll
    for (int i = 0; i < 8; i++) { x[i] = __expf(x[i] - m); s += x[i]; }
    #pragma unroll
    for (int o = 16; o > 0; o >>= 1)
        s += __shfl_xor_sync(0xffffffffu, s, o);
    if ((t & 31) == 0) ss[t >> 5] = s;
    __syncthreads();
    s = (ss[0] + ss[1] + ss[2] + ss[3]) + (ss[4] + ss[5] + ss[6] + ss[7]);

    float inv = 1.0f / s;
    #pragma unroll
    for (int i = 0; i < 8; i++) hp[i] = __float2half_rn(x[i] * inv);
    *(uint4*)&p[t * 8] = raw;
}

// ---------------------------------------------------------------------------
extern "C" void kernel_launch(void* const* d_in, const int* in_sizes, int n_in,
                              void* d_out, int out_size)
{
    const float* X  = (const float*)d_in[0];
    const float* Wq = (const float*)d_in[1];
    const float* bq = (const float*)d_in[2];
    const float* Wk = (const float*)d_in[3];
    const float* bk = (const float*)d_in[4];
    const float* Wv = (const float*)d_in[5];
    const float* bv = (const float*)d_in[6];
    float* out = (float*)d_out;

    __half *q, *k, *v;
    float* s;
    cudaGetSymbolAddress((void**)&q, g_q);
    cudaGetSymbolAddress((void**)&k, g_k);
    cudaGetSymbolAddress((void**)&v, g_v);
    cudaGetSymbolAddress((void**)&s, g_s);

    cudaFuncSetAttribute(gemm_fp16<false, true, true>,
                         cudaFuncAttributeMaxDynamicSharedMemorySize, SMEM_BYTES);
    cudaFuncSetAttribute(gemm_fp16<true, true, false>,
                         cudaFuncAttributeMaxDynamicSharedMemorySize, SMEM_BYTES);
    cudaFuncSetAttribute(gemm_fp16<false, false, false>,
                         cudaFuncAttributeMaxDynamicSharedMemorySize, SMEM_BYTES);

    const long long TD = (long long)SEQ * DIM;   // 2097152
    const long long TT = (long long)SEQ * SEQ;   // 4194304

    // Half scratch inside g_s until phase 2 overwrites it with half scores:
    __half* Xh  = (__half*)s;                                  // 16M halves
    __half* Wqh = (__half*)(s + (long long)MTOT * DIM / 2);
    __half* Wkh = Wqh + (long long)DIM * DIM;
    __half* Wvh = Wkh + (long long)DIM * DIM;
    __half* Sh  = (__half*)s;                                  // scores/P (64 MB)

    // Phase 0: convert all inputs to half in one launch
    cvt_f2h_all<<<2464, 256>>>((const float4*)X,  (uint4*)Xh,
                               (const float4*)Wq, (uint4*)Wqh,
                               (const float4*)Wk, (uint4*)Wkh,
                               (const float4*)Wv, (uint4*)Wvh);

    // Phase 1: fused Q/K/V projections (z selects W/bias/out)
    {
        dim3 grid(DIM / BN, MTOT / BM, 3);  // (8, 128, 3)
        gemm_fp16<false, true, true><<<grid, 256, SMEM_BYTES>>>(
            Xh, Wqh, bq, q, DIM, DIM, DIM, DIM, 0, 0, 0, 1.0f,
            Wkh, Wvh, bk, bv, k, v);
    }

    // Phase 2: scores = (Q @ K^T) / 32, written as HALF
    {
        dim3 grid(SEQ / BN, SEQ / BM, BATCH);  // (16, 16, 8)
        gemm_fp16<true, true, false><<<grid, 256, SMEM_BYTES>>>(
            q, k, nullptr, Sh, DIM, DIM, DIM, SEQ, TD, TD, TT, 0.03125f);
    }

    // Phase 3: softmax on half scores, in place
    softmax2048h<<<MTOT, 256>>>(Sh);

    // Phase 4: out = P @ V (A = half P, contiguous lda = SEQ)
    {
        dim3 grid(DIM / BN, SEQ / BM, BATCH);  // (8, 16, 8)
        gemm_fp16<false, false, false><<<grid, 256, SMEM_BYTES>>>(
            Sh, v, nullptr, out, SEQ, SEQ, DIM, DIM, TT, TD, TD, 1.0f);
    }
}

// round 13
// speedup vs baseline: 1.7395x; 1.0024x over previous
#include <cuda_runtime.h>
#include <cstdint>
#include <cuda_fp16.h>
#include <mma.h>

using namespace nvcuda;

// Problem constants
#define BATCH 8
#define SEQ   2048
#define DIM   1024
#define MTOT  (BATCH * SEQ)        // 16384

// GEMM tiling: CTA 128x128, warp 64x32, K-chunk 64, double-buffered cp.async
#define BM 128
#define BN 128
#define BK 64
#define AKP 72                       // A row stride (halves) = 144 B
#define BKP 72                       // B trans row stride
#define BNP 136                      // B non-trans row stride = 272 B
#define A_STAGE 9216                 // 128*72 halves
#define B_STAGE 9216                 // max(128*72, 64*136) halves
#define STAGE_HALVES (A_STAGE + B_STAGE)
#define SMEM_BYTES (2 * STAGE_HALVES * 2)   // 73728 B (2 CTAs/SM = 144KB)

// Scratch (__device__ globals; allocation-free rule).
// g_x/g_w are DISJOINT from g_s so the forked V-projection can read them
// while phase 2 writes scores into g_s (the R12 race is gone).
__device__ __half g_x[(long long)MTOT * DIM];        // 32 MB  (Xh)
__device__ __half g_w[3LL * DIM * DIM];              //  6 MB  (Wq,Wk,Wv half)
__device__ __half g_q[(long long)MTOT * DIM];        // 32 MB
__device__ __half g_k[(long long)MTOT * DIM];        // 32 MB
__device__ __half g_v[(long long)MTOT * DIM];        // 32 MB
__device__ __half g_s[(long long)MTOT * SEQ];        // 64 MB  (half scores / P)

__device__ __forceinline__ void cp16(void* smem, const void* gmem) {
    unsigned s = (unsigned)__cvta_generic_to_shared(smem);
    asm volatile("cp.async.cg.shared.global [%0], [%1], 16;\n" :: "r"(s), "l"(gmem));
}
#define CP_COMMIT() asm volatile("cp.async.commit_group;\n")

// ---------------------------------------------------------------------------
// FP16 WMMA GEMM (fp32 accumulate), double-buffered cp.async, 64x32 warp tiles.
//   C[M,N] = scale * (A[M,K] @ B(^T)) (+ bias, HALF_OUT only)
//   QKV3: blockIdx.z selects (B, bias, C) among up to 3 sets; A shared.
// ---------------------------------------------------------------------------
template <bool TRANSB, bool HALF_OUT, bool QKV3>
__global__ __launch_bounds__(256, 2)
void gemm_fp16(const __half* __restrict__ Ab, const __half* __restrict__ Bb,
               const float* __restrict__ bias, void* __restrict__ Cb,
               int K, int lda, int ldb, int ldc,
               long long sA, long long sB, long long sC, float scale,
               const __half* __restrict__ Bb1 = nullptr,
               const __half* __restrict__ Bb2 = nullptr,
               const float* __restrict__ bias1 = nullptr,
               const float* __restrict__ bias2 = nullptr,
               void* __restrict__ Cb1 = nullptr,
               void* __restrict__ Cb2 = nullptr)
{
    extern __shared__ __half sh[];
    __shared__ float epi[8][16 * 20];
    __shared__ float biasS[BN];

    const __half* A = Ab;
    const __half* B = Bb;
    const float*  bi = bias;
    void*         Cv = Cb;

    if constexpr (QKV3) {
        if (blockIdx.z == 1)      { B = Bb1; bi = bias1; Cv = Cb1; }
        else if (blockIdx.z == 2) { B = Bb2; bi = bias2; Cv = Cb2; }
    } else {
        A += (long long)blockIdx.z * sA;
        B += (long long)blockIdx.z * sB;
    }

    const int m0 = blockIdx.y * BM;
    const int n0 = blockIdx.x * BN;
    const int t  = threadIdx.x;
    const int warp = t >> 5;
    const int lid  = t & 31;
    const int wm = warp >> 2;   // 0..1 (64-row slab)
    const int wn = warp & 3;    // 0..3 (32-col slab)

    if (HALF_OUT && t < BN) biasS[t] = bi ? bi[n0 + t] : 0.0f;

    wmma::fragment<wmma::accumulator, 16, 16, 16, float> acc[4][2];
    #pragma unroll
    for (int mi = 0; mi < 4; mi++)
        #pragma unroll
        for (int nj = 0; nj < 2; nj++)
            wmma::fill_fragment(acc[mi][nj], 0.0f);

    // Stage one K=64 chunk into buffer slot b (0/1)
    auto stage = [&](int chunk, int b) {
        const int k0 = chunk * BK;
        __half* Ad = sh + b * STAGE_HALVES;
        __half* Bd = Ad + A_STAGE;
        #pragma unroll
        for (int j = 0; j < 4; j++) {              // A: 128x64 = 1024 cp16
            int idx = t + 256 * j;
            int r  = idx >> 3;                     // 0..127
            int c8 = (idx & 7) << 3;               // 0..56
            cp16(&Ad[r * AKP + c8], &A[(long long)(m0 + r) * lda + k0 + c8]);
        }
        if (TRANSB) {
            #pragma unroll
            for (int j = 0; j < 4; j++) {          // B: 128x64 = 1024 cp16
                int idx = t + 256 * j;
                int r  = idx >> 3;
                int c8 = (idx & 7) << 3;
                cp16(&Bd[r * BKP + c8], &B[(long long)(n0 + r) * ldb + k0 + c8]);
            }
        } else {
            #pragma unroll
            for (int j = 0; j < 4; j++) {          // B: 64x128 = 1024 cp16
                int idx = t + 256 * j;
                int r  = idx >> 4;                 // 0..63
                int c8 = (idx & 15) << 3;          // 0..120
                cp16(&Bd[r * BNP + c8], &B[(long long)(k0 + r) * ldb + n0 + c8]);
            }
        }
        CP_COMMIT();
    };

    const int nchunk = K / BK;
    stage(0, 0);

    int cur = 0;
    for (int i = 0; i < nchunk; i++) {
        if (i + 1 < nchunk) {
            stage(i + 1, cur ^ 1);
            asm volatile("cp.async.wait_group 1;\n");
        } else {
            asm volatile("cp.async.wait_group 0;\n");
        }
        __syncthreads();

        const __half* Ac = sh + cur * STAGE_HALVES;
        const __half* Bc = Ac + A_STAGE;

        #pragma unroll
        for (int kk = 0; kk < BK; kk += 16) {
            wmma::fragment<wmma::matrix_a, 16, 16, 16, __half, wmma::row_major> af[4];
            #pragma unroll
            for (int mi = 0; mi < 4; mi++)
                wmma::load_matrix_sync(af[mi], &Ac[(wm * 64 + mi * 16) * AKP + kk], AKP);

            #pragma unroll
            for (int nj = 0; nj < 2; nj++) {
                if constexpr (TRANSB) {
                    wmma::fragment<wmma::matrix_b, 16, 16, 16, __half,
                                   wmma::col_major> bf;
                    wmma::load_matrix_sync(bf, &Bc[(wn * 32 + nj * 16) * BKP + kk], BKP);
                    #pragma unroll
                    for (int mi = 0; mi < 4; mi++)
                        wmma::mma_sync(acc[mi][nj], af[mi], bf, acc[mi][nj]);
                } else {
                    wmma::fragment<wmma::matrix_b, 16, 16, 16, __half,
                                   wmma::row_major> bf;
                    wmma::load_matrix_sync(bf, &Bc[kk * BNP + wn * 32 + nj * 16], BNP);
                    #pragma unroll
                    for (int mi = 0; mi < 4; mi++)
                        wmma::mma_sync(acc[mi][nj], af[mi], bf, acc[mi][nj]);
                }
            }
        }
        __syncthreads();
        cur ^= 1;
    }

    // Epilogue
    if constexpr (!HALF_OUT) {
        float* C = (float*)Cv + (QKV3 ? 0LL : (long long)blockIdx.z * sC);
        #pragma unroll
        for (int mi = 0; mi < 4; mi++)
            #pragma unroll
            for (int nj = 0; nj < 2; nj++) {
                if (scale != 1.0f) {
                    #pragma unroll
                    for (int e = 0; e < acc[mi][nj].num_elements; e++)
                        acc[mi][nj].x[e] *= scale;
                }
                wmma::store_matrix_sync(
                    &C[(long long)(m0 + wm * 64 + mi * 16) * ldc + n0 + wn * 32 + nj * 16],
                    acc[mi][nj], ldc, wmma::mem_row_major);
            }
    } else {
        __half* C = (__half*)Cv + (QKV3 ? 0LL : (long long)blockIdx.z * sC);
        float* ep = epi[warp];
        const int r  = lid >> 1;          // 0..15
        const int ch = (lid & 1) * 8;     // 0 or 8
        #pragma unroll
        for (int mi = 0; mi < 4; mi++)
            #pragma unroll
            for (int nj = 0; nj < 2; nj++) {
                wmma::store_matrix_sync(ep, acc[mi][nj], 20, wmma::mem_row_major);
                __syncwarp();
                const int colb = wn * 32 + nj * 16 + ch;
                __half h[8];
                #pragma unroll
                for (int i = 0; i < 8; i++)
                    h[i] = __float2half_rn(ep[r * 20 + ch + i] * scale + biasS[colb + i]);
                *(uint4*)&C[(long long)(m0 + wm * 64 + mi * 16 + r) * ldc + n0 + colb] =
                    *(uint4*)h;
                __syncwarp();
            }
    }
}

// ---------------------------------------------------------------------------
// Fused float->half conversion of X, Wq, Wk, Wv in ONE launch.
// ---------------------------------------------------------------------------
__global__ __launch_bounds__(256)
void cvt_f2h_all(const float4* __restrict__ X,  uint4* __restrict__ Xo,
                 const float4* __restrict__ W0, uint4* __restrict__ W0o,
                 const float4* __restrict__ W1, uint4* __restrict__ W1o,
                 const float4* __restrict__ W2, uint4* __restrict__ W2o)
{
    const int NX = MTOT * DIM / 8;     // 2097152
    const int NW = DIM * DIM / 8;      // 131072
    const int total = NX + 3 * NW;
    for (int i = blockIdx.x * blockDim.x + threadIdx.x; i < total;
         i += gridDim.x * blockDim.x) {
        const float4* in; uint4* out; int j;
        if (i < NX)                { in = X;  out = Xo;  j = i; }
        else if (i < NX + NW)      { in = W0; out = W0o; j = i - NX; }
        else if (i < NX + 2 * NW)  { in = W1; out = W1o; j = i - NX - NW; }
        else                       { in = W2; out = W2o; j = i - NX - 2 * NW; }
        float4 a = in[j * 2], b = in[j * 2 + 1];
        __half h[8];
        h[0] = __float2half_rn(a.x); h[1] = __float2half_rn(a.y);
        h[2] = __float2half_rn(a.z); h[3] = __float2half_rn(a.w);
        h[4] = __float2half_rn(b.x); h[5] = __float2half_rn(b.y);
        h[6] = __float2half_rn(b.z); h[7] = __float2half_rn(b.w);
        out[j] = *(uint4*)h;
    }
}

// ---------------------------------------------------------------------------
// Row softmax over 2048 HALF scores, fp32 math, writes half in place.
// ---------------------------------------------------------------------------
__global__ __launch_bounds__(256)
void softmax2048h(__half* __restrict__ S)
{
    __half* p = S + (long long)blockIdx.x * SEQ;
    const int t = threadIdx.x;

    uint4 raw = *(const uint4*)&p[t * 8];
    __half* hp = (__half*)&raw;
    float x[8];
    #pragma unroll
    for (int i = 0; i < 8; i++) x[i] = __half2float(hp[i]);

    float m = x[0];
    #pragma unroll
    for (int i = 1; i < 8; i++) m = fmaxf(m, x[i]);
    #pragma unroll
    for (int o = 16; o > 0; o >>= 1)
        m = fmaxf(m, __shfl_xor_sync(0xffffffffu, m, o));

    __shared__ float sm[8], ss[8];
    if ((t & 31) == 0) sm[t >> 5] = m;
    __syncthreads();
    m = fmaxf(fmaxf(fmaxf(sm[0], sm[1]), fmaxf(sm[2], sm[3])),
              fmaxf(fmaxf(sm[4], sm[5]), fmaxf(sm[6], sm[7])));

    float s = 0.0f;
    #pragma unroll
    for (int i = 0; i < 8; i++) { x[i] = __expf(x[i] - m); s += x[i]; }
    #pragma unroll
    for (int o = 16; o > 0; o >>= 1)
        s += __shfl_xor_sync(0xffffffffu, s, o);
    if ((t & 31) == 0) ss[t >> 5] = s;
    __syncthreads();
    s = (ss[0] + ss[1] + ss[2] + ss[3]) + (ss[4] + ss[5] + ss[6] + ss[7]);

    float inv = 1.0f / s;
    #pragma unroll
    for (int i = 0; i < 8; i++) hp[i] = __float2half_rn(x[i] * inv);
    *(uint4*)&p[t * 8] = raw;
}

// ---------------------------------------------------------------------------
extern "C" void kernel_launch(void* const* d_in, const int* in_sizes, int n_in,
                              void* d_out, int out_size)
{
    const float* X  = (const float*)d_in[0];
    const float* Wq = (const float*)d_in[1];
    const float* bq = (const float*)d_in[2];
    const float* Wk = (const float*)d_in[3];
    const float* bk = (const float*)d_in[4];
    const float* Wv = (const float*)d_in[5];
    const float* bv = (const float*)d_in[6];
    float* out = (float*)d_out;

    __half *xh, *wh, *q, *k, *v, *sh_;
    cudaGetSymbolAddress((void**)&xh, g_x);
    cudaGetSymbolAddress((void**)&wh, g_w);
    cudaGetSymbolAddress((void**)&q, g_q);
    cudaGetSymbolAddress((void**)&k, g_k);
    cudaGetSymbolAddress((void**)&v, g_v);
    cudaGetSymbolAddress((void**)&sh_, g_s);

    __half* Wqh = wh;
    __half* Wkh = wh + (long long)DIM * DIM;
    __half* Wvh = wh + 2LL * DIM * DIM;
    __half* Sh  = sh_;

    // One-time host-side resources (no device memory involved).
    static cudaStream_t s1 = nullptr;
    static cudaEvent_t  evQK = nullptr, evV = nullptr;
    if (s1 == nullptr) {
        cudaStreamCreateWithFlags(&s1, cudaStreamNonBlocking);
        cudaEventCreateWithFlags(&evQK, cudaEventDisableTiming);
        cudaEventCreateWithFlags(&evV,  cudaEventDisableTiming);
    }

    cudaFuncSetAttribute(gemm_fp16<false, true, true>,
                         cudaFuncAttributeMaxDynamicSharedMemorySize, SMEM_BYTES);
    cudaFuncSetAttribute(gemm_fp16<true, true, false>,
                         cudaFuncAttributeMaxDynamicSharedMemorySize, SMEM_BYTES);
    cudaFuncSetAttribute(gemm_fp16<false, false, false>,
                         cudaFuncAttributeMaxDynamicSharedMemorySize, SMEM_BYTES);

    const long long TD = (long long)SEQ * DIM;   // 2097152
    const long long TT = (long long)SEQ * SEQ;   // 4194304

    // Phase 0: convert all inputs to half (into DEDICATED buffers g_x/g_w)
    cvt_f2h_all<<<2464, 256>>>((const float4*)X,  (uint4*)xh,
                               (const float4*)Wq, (uint4*)Wqh,
                               (const float4*)Wk, (uint4*)Wkh,
                               (const float4*)Wv, (uint4*)Wvh);

    // Phase 1a: Q and K projections (z in {0,1}) on capture stream
    {
        dim3 grid(DIM / BN, MTOT / BM, 2);  // (8, 128, 2)
        gemm_fp16<false, true, true><<<grid, 256, SMEM_BYTES>>>(
            xh, Wqh, bq, q, DIM, DIM, DIM, DIM, 0, 0, 0, 1.0f,
            Wkh, nullptr, bk, nullptr, k, nullptr);
    }

    // Fork: V projection on s1, concurrent with phase 2 + softmax.
    // Reads g_x/g_w, writes g_v — fully disjoint from phase 2's g_q/g_k/g_s.
    cudaEventRecord(evQK, 0);
    cudaStreamWaitEvent(s1, evQK, 0);
    {
        dim3 grid(DIM / BN, MTOT / BM, 1);  // (8, 128, 1)
        gemm_fp16<false, true, true><<<grid, 256, SMEM_BYTES, s1>>>(
            xh, Wvh, bv, v, DIM, DIM, DIM, DIM, 0, 0, 0, 1.0f,
            nullptr, nullptr, nullptr, nullptr, nullptr, nullptr);
    }
    cudaEventRecord(evV, s1);

    // Phase 2: scores = (Q @ K^T) / 32, written as HALF into g_s
    {
        dim3 grid(SEQ / BN, SEQ / BM, BATCH);  // (16, 16, 8)
        gemm_fp16<true, true, false><<<grid, 256, SMEM_BYTES>>>(
            q, k, nullptr, Sh, DIM, DIM, DIM, SEQ, TD, TD, TT, 0.03125f);
    }

    // Phase 3: softmax on half scores, in place
    softmax2048h<<<MTOT, 256>>>(Sh);

    // Join: phase 4 needs V
    cudaStreamWaitEvent(0, evV, 0);

    // Phase 4: out = P @ V (A = half P, contiguous lda = SEQ)
    {
        dim3 grid(DIM / BN, SEQ / BM, BATCH);  // (8, 16, 8)
        gemm_fp16<false, false, false><<<grid, 256, SMEM_BYTES>>>(
            Sh, v, nullptr, out, SEQ, SEQ, DIM, DIM, TT, TD, TD, 1.0f);
    }
}

// round 14
// speedup vs baseline: 1.9419x; 1.1164x over previous
#include <cuda_runtime.h>
#include <cstdint>
#include <cuda_fp16.h>
#include <mma.h>

using namespace nvcuda;

// Problem constants
#define BATCH 8
#define SEQ   2048
#define DIM   1024
#define MTOT  (BATCH * SEQ)        // 16384

// GEMM tiling: CTA 128x128, warp 64x32, K-chunk 64, double-buffered cp.async
#define BM 128
#define BN 128
#define BK 64
#define AKP 72                       // A row stride (halves) = 144 B
#define BKP 72                       // B trans row stride
#define BNP 136                      // B non-trans row stride = 272 B
#define A_STAGE 9216                 // 128*72 halves
#define B_STAGE 9216                 // max(128*72, 64*136) halves
#define STAGE_HALVES (A_STAGE + B_STAGE)
#define SMEM_BYTES (2 * STAGE_HALVES * 2)   // 73728 B (2 CTAs/SM = 144KB)

// Scratch (__device__ globals; allocation-free rule)
__device__ __half g_x[(long long)MTOT * DIM];   // 32 MB  Xh
__device__ __half g_w[3LL * DIM * DIM];         //  6 MB  Wq,Wk,Wv half
__device__ __half g_m[(long long)DIM * DIM];    //  2 MB  M = Wq Wk^T (half)
__device__ __half g_xm[(long long)MTOT * DIM];  // 32 MB  XM (half)
__device__ __half g_v[(long long)MTOT * DIM];   // 32 MB  V
__device__ __half g_s[(long long)MTOT * SEQ];   // 64 MB  half scores / P
__device__ float  g_bvec[DIM];                  // Wk@bq / 32
__device__ float  g_beta[MTOT];                 // X @ bvec  (pre-scaled by 1/32)

__device__ __forceinline__ void cp16(void* smem, const void* gmem) {
    unsigned s = (unsigned)__cvta_generic_to_shared(smem);
    asm volatile("cp.async.cg.shared.global [%0], [%1], 16;\n" :: "r"(s), "l"(gmem));
}
#define CP_COMMIT() asm volatile("cp.async.commit_group;\n")

// ---------------------------------------------------------------------------
// FP16 WMMA GEMM (fp32 accumulate), double-buffered cp.async, 64x32 warp tiles.
//   C[M,N] = scale * (A[M,K] @ B(^T)) (+ bias, HALF_OUT only)
//   QKV3: blockIdx.z selects (B, bias, C) among up to 3 sets; A shared.
//   sBias: per-z element offset into bias (batched column bias, e.g. beta).
// ---------------------------------------------------------------------------
template <bool TRANSB, bool HALF_OUT, bool QKV3>
__global__ __launch_bounds__(256, 2)
void gemm_fp16(const __half* __restrict__ Ab, const __half* __restrict__ Bb,
               const float* __restrict__ bias, void* __restrict__ Cb,
               int K, int lda, int ldb, int ldc,
               long long sA, long long sB, long long sC, float scale,
               const __half* __restrict__ Bb1 = nullptr,
               const __half* __restrict__ Bb2 = nullptr,
               const float* __restrict__ bias1 = nullptr,
               const float* __restrict__ bias2 = nullptr,
               void* __restrict__ Cb1 = nullptr,
               void* __restrict__ Cb2 = nullptr,
               long long sBias = 0)
{
    extern __shared__ __half sh[];
    __shared__ float epi[8][16 * 20];
    __shared__ float biasS[BN];

    const __half* A = Ab;
    const __half* B = Bb;
    const float*  bi = bias;
    void*         Cv = Cb;

    if constexpr (QKV3) {
        if (blockIdx.z == 1)      { B = Bb1; bi = bias1; Cv = Cb1; }
        else if (blockIdx.z == 2) { B = Bb2; bi = bias2; Cv = Cb2; }
    } else {
        A += (long long)blockIdx.z * sA;
        B += (long long)blockIdx.z * sB;
        if (bi) bi += (long long)blockIdx.z * sBias;
    }

    const int m0 = blockIdx.y * BM;
    const int n0 = blockIdx.x * BN;
    const int t  = threadIdx.x;
    const int warp = t >> 5;
    const int lid  = t & 31;
    const int wm = warp >> 2;   // 0..1 (64-row slab)
    const int wn = warp & 3;    // 0..3 (32-col slab)

    if (HALF_OUT && t < BN) biasS[t] = bi ? bi[n0 + t] : 0.0f;

    wmma::fragment<wmma::accumulator, 16, 16, 16, float> acc[4][2];
    #pragma unroll
    for (int mi = 0; mi < 4; mi++)
        #pragma unroll
        for (int nj = 0; nj < 2; nj++)
            wmma::fill_fragment(acc[mi][nj], 0.0f);

    // Stage one K=64 chunk into buffer slot b (0/1)
    auto stage = [&](int chunk, int b) {
        const int k0 = chunk * BK;
        __half* Ad = sh + b * STAGE_HALVES;
        __half* Bd = Ad + A_STAGE;
        #pragma unroll
        for (int j = 0; j < 4; j++) {              // A: 128x64 = 1024 cp16
            int idx = t + 256 * j;
            int r  = idx >> 3;                     // 0..127
            int c8 = (idx & 7) << 3;               // 0..56
            cp16(&Ad[r * AKP + c8], &A[(long long)(m0 + r) * lda + k0 + c8]);
        }
        if (TRANSB) {
            #pragma unroll
            for (int j = 0; j < 4; j++) {          // B: 128x64 = 1024 cp16
                int idx = t + 256 * j;
                int r  = idx >> 3;
                int c8 = (idx & 7) << 3;
                cp16(&Bd[r * BKP + c8], &B[(long long)(n0 + r) * ldb + k0 + c8]);
            }
        } else {
            #pragma unroll
            for (int j = 0; j < 4; j++) {          // B: 64x128 = 1024 cp16
                int idx = t + 256 * j;
                int r  = idx >> 4;                 // 0..63
                int c8 = (idx & 15) << 3;          // 0..120
                cp16(&Bd[r * BNP + c8], &B[(long long)(k0 + r) * ldb + n0 + c8]);
            }
        }
        CP_COMMIT();
    };

    const int nchunk = K / BK;
    stage(0, 0);

    int cur = 0;
    for (int i = 0; i < nchunk; i++) {
        if (i + 1 < nchunk) {
            stage(i + 1, cur ^ 1);
            asm volatile("cp.async.wait_group 1;\n");
        } else {
            asm volatile("cp.async.wait_group 0;\n");
        }
        __syncthreads();

        const __half* Ac = sh + cur * STAGE_HALVES;
        const __half* Bc = Ac + A_STAGE;

        #pragma unroll
        for (int kk = 0; kk < BK; kk += 16) {
            wmma::fragment<wmma::matrix_a, 16, 16, 16, __half, wmma::row_major> af[4];
            #pragma unroll
            for (int mi = 0; mi < 4; mi++)
                wmma::load_matrix_sync(af[mi], &Ac[(wm * 64 + mi * 16) * AKP + kk], AKP);

            #pragma unroll
            for (int nj = 0; nj < 2; nj++) {
                if constexpr (TRANSB) {
                    wmma::fragment<wmma::matrix_b, 16, 16, 16, __half,
                                   wmma::col_major> bf;
                    wmma::load_matrix_sync(bf, &Bc[(wn * 32 + nj * 16) * BKP + kk], BKP);
                    #pragma unroll
                    for (int mi = 0; mi < 4; mi++)
                        wmma::mma_sync(acc[mi][nj], af[mi], bf, acc[mi][nj]);
                } else {
                    wmma::fragment<wmma::matrix_b, 16, 16, 16, __half,
                                   wmma::row_major> bf;
                    wmma::load_matrix_sync(bf, &Bc[kk * BNP + wn * 32 + nj * 16], BNP);
                    #pragma unroll
                    for (int mi = 0; mi < 4; mi++)
                        wmma::mma_sync(acc[mi][nj], af[mi], bf, acc[mi][nj]);
                }
            }
        }
        __syncthreads();
        cur ^= 1;
    }

    // Epilogue
    if constexpr (!HALF_OUT) {
        float* C = (float*)Cv + (QKV3 ? 0LL : (long long)blockIdx.z * sC);
        #pragma unroll
        for (int mi = 0; mi < 4; mi++)
            #pragma unroll
            for (int nj = 0; nj < 2; nj++) {
                if (scale != 1.0f) {
                    #pragma unroll
                    for (int e = 0; e < acc[mi][nj].num_elements; e++)
                        acc[mi][nj].x[e] *= scale;
                }
                wmma::store_matrix_sync(
                    &C[(long long)(m0 + wm * 64 + mi * 16) * ldc + n0 + wn * 32 + nj * 16],
                    acc[mi][nj], ldc, wmma::mem_row_major);
            }
    } else {
        __half* C = (__half*)Cv + (QKV3 ? 0LL : (long long)blockIdx.z * sC);
        float* ep = epi[warp];
        const int r  = lid >> 1;          // 0..15
        const int ch = (lid & 1) * 8;     // 0 or 8
        #pragma unroll
        for (int mi = 0; mi < 4; mi++)
            #pragma unroll
            for (int nj = 0; nj < 2; nj++) {
                wmma::store_matrix_sync(ep, acc[mi][nj], 20, wmma::mem_row_major);
                __syncwarp();
                const int colb = wn * 32 + nj * 16 + ch;
                __half h[8];
                #pragma unroll
                for (int i = 0; i < 8; i++)
                    h[i] = __float2half_rn(ep[r * 20 + ch + i] * scale + biasS[colb + i]);
                *(uint4*)&C[(long long)(m0 + wm * 64 + mi * 16 + r) * ldc + n0 + colb] =
                    *(uint4*)h;
                __syncwarp();
            }
    }
}

// ---------------------------------------------------------------------------
// Fused float->half conversion of X, Wq, Wk, Wv in ONE launch.
// ---------------------------------------------------------------------------
__global__ __launch_bounds__(256)
void cvt_f2h_all(const float4* __restrict__ X,  uint4* __restrict__ Xo,
                 const float4* __restrict__ W0, uint4* __restrict__ W0o,
                 const float4* __restrict__ W1, uint4* __restrict__ W1o,
                 const float4* __restrict__ W2, uint4* __restrict__ W2o)
{
    const int NX = MTOT * DIM / 8;     // 2097152
    const int NW = DIM * DIM / 8;      // 131072
    const int total = NX + 3 * NW;
    for (int i = blockIdx.x * blockDim.x + threadIdx.x; i < total;
         i += gridDim.x * blockDim.x) {
        const float4* in; uint4* out; int j;
        if (i < NX)                { in = X;  out = Xo;  j = i; }
        else if (i < NX + NW)      { in = W0; out = W0o; j = i - NX; }
        else if (i < NX + 2 * NW)  { in = W1; out = W1o; j = i - NX - NW; }
        else                       { in = W2; out = W2o; j = i - NX - 2 * NW; }
        float4 a = in[j * 2], b = in[j * 2 + 1];
        __half h[8];
        h[0] = __float2half_rn(a.x); h[1] = __float2half_rn(a.y);
        h[2] = __float2half_rn(a.z); h[3] = __float2half_rn(a.w);
        h[4] = __float2half_rn(b.x); h[5] = __float2half_rn(b.y);
        h[6] = __float2half_rn(b.z); h[7] = __float2half_rn(b.w);
        out[j] = *(uint4*)h;
    }
}

// ---------------------------------------------------------------------------
// bvec = (Wk @ bq) / 32  — one warp per row of Wk (fp32 input)
// ---------------------------------------------------------------------------
__global__ __launch_bounds__(256)
void gemv_wkbq(const float* __restrict__ Wk, const float* __restrict__ bq,
               float* __restrict__ bvec)
{
    int row  = (blockIdx.x * blockDim.x + threadIdx.x) >> 5;
    int lane = threadIdx.x & 31;
    if (row >= DIM) return;
    const float* w = Wk + (long long)row * DIM;
    float acc = 0.0f;
    for (int d = lane; d < DIM; d += 32) acc += w[d] * bq[d];
    #pragma unroll
    for (int o = 16; o > 0; o >>= 1) acc += __shfl_xor_sync(0xffffffffu, acc, o);
    if (lane == 0) bvec[row] = acc * 0.03125f;
}

// ---------------------------------------------------------------------------
// beta[j] = Xh[j,:] . bvec  — one warp per row of Xh (beta pre-scaled by 1/32)
// ---------------------------------------------------------------------------
__global__ __launch_bounds__(256)
void gemv_beta(const __half* __restrict__ Xh, const float* __restrict__ bvec,
               float* __restrict__ beta)
{
    int row  = (blockIdx.x * blockDim.x + threadIdx.x) >> 5;
    int lane = threadIdx.x & 31;
    if (row >= MTOT) return;
    const __half2* x = (const __half2*)(Xh + (long long)row * DIM);
    float acc = 0.0f;
    for (int d = lane; d < DIM / 2; d += 32) {
        float2 xv = __half22float2(x[d]);
        acc += xv.x * bvec[2 * d] + xv.y * bvec[2 * d + 1];
    }
    #pragma unroll
    for (int o = 16; o > 0; o >>= 1) acc += __shfl_xor_sync(0xffffffffu, acc, o);
    if (lane == 0) beta[row] = acc;
}

// ---------------------------------------------------------------------------
// Row softmax over 2048 HALF scores, fp32 math, writes half in place.
// ---------------------------------------------------------------------------
__global__ __launch_bounds__(256)
void softmax2048h(__half* __restrict__ S)
{
    __half* p = S + (long long)blockIdx.x * SEQ;
    const int t = threadIdx.x;

    uint4 raw = *(const uint4*)&p[t * 8];
    __half* hp = (__half*)&raw;
    float x[8];
    #pragma unroll
    for (int i = 0; i < 8; i++) x[i] = __half2float(hp[i]);

    float m = x[0];
    #pragma unroll
    for (int i = 1; i < 8; i++) m = fmaxf(m, x[i]);
    #pragma unroll
    for (int o = 16; o > 0; o >>= 1)
        m = fmaxf(m, __shfl_xor_sync(0xffffffffu, m, o));

    __shared__ float sm[8], ss[8];
    if ((t & 31) == 0) sm[t >> 5] = m;
    __syncthreads();
    m = fmaxf(fmaxf(fmaxf(sm[0], sm[1]), fmaxf(sm[2], sm[3])),
              fmaxf(fmaxf(sm[4], sm[5]), fmaxf(sm[6], sm[7])));

    float s = 0.0f;
    #pragma unroll
    for (int i = 0; i < 8; i++) { x[i] = __expf(x[i] - m); s += x[i]; }
    #pragma unroll
    for (int o = 16; o > 0; o >>= 1)
        s += __shfl_xor_sync(0xffffffffu, s, o);
    if ((t & 31) == 0) ss[t >> 5] = s;
    __syncthreads();
    s = (ss[0] + ss[1] + ss[2] + ss[3]) + (ss[4] + ss[5] + ss[6] + ss[7]);

    float inv = 1.0f / s;
    #pragma unroll
    for (int i = 0; i < 8; i++) hp[i] = __float2half_rn(x[i] * inv);
    *(uint4*)&p[t * 8] = raw;
}

// ---------------------------------------------------------------------------
extern "C" void kernel_launch(void* const* d_in, const int* in_sizes, int n_in,
                              void* d_out, int out_size)
{
    const float* X  = (const float*)d_in[0];
    const float* Wq = (const float*)d_in[1];
    const float* bq = (const float*)d_in[2];
    const float* Wk = (const float*)d_in[3];
    const float* bk = (const float*)d_in[4];
    const float* Wv = (const float*)d_in[5];
    const float* bv = (const float*)d_in[6];
    float* out = (float*)d_out;
    (void)bk;   // cancels in softmax (row-constant term)

    __half *xh, *wh, *mh, *xm, *v, *sh_;
    float *bvec, *beta;
    cudaGetSymbolAddress((void**)&xh, g_x);
    cudaGetSymbolAddress((void**)&wh, g_w);
    cudaGetSymbolAddress((void**)&mh, g_m);
    cudaGetSymbolAddress((void**)&xm, g_xm);
    cudaGetSymbolAddress((void**)&v, g_v);
    cudaGetSymbolAddress((void**)&sh_, g_s);
    cudaGetSymbolAddress((void**)&bvec, g_bvec);
    cudaGetSymbolAddress((void**)&beta, g_beta);

    __half* Wqh = wh;
    __half* Wkh = wh + (long long)DIM * DIM;
    __half* Wvh = wh + 2LL * DIM * DIM;
    __half* Sh  = sh_;

    // One-time host-side resources (no device memory involved).
    static cudaStream_t s1 = nullptr;
    static cudaEvent_t evCvt = nullptr, evBeta = nullptr, evV = nullptr;
    if (s1 == nullptr) {
        cudaStreamCreateWithFlags(&s1, cudaStreamNonBlocking);
        cudaEventCreateWithFlags(&evCvt,  cudaEventDisableTiming);
        cudaEventCreateWithFlags(&evBeta, cudaEventDisableTiming);
        cudaEventCreateWithFlags(&evV,    cudaEventDisableTiming);
    }

    cudaFuncSetAttribute(gemm_fp16<false, true, true>,
                         cudaFuncAttributeMaxDynamicSharedMemorySize, SMEM_BYTES);
    cudaFuncSetAttribute(gemm_fp16<true, true, false>,
                         cudaFuncAttributeMaxDynamicSharedMemorySize, SMEM_BYTES);
    cudaFuncSetAttribute(gemm_fp16<false, true, false>,
                         cudaFuncAttributeMaxDynamicSharedMemorySize, SMEM_BYTES);
    cudaFuncSetAttribute(gemm_fp16<false, false, false>,
                         cudaFuncAttributeMaxDynamicSharedMemorySize, SMEM_BYTES);

    const long long TD = (long long)SEQ * DIM;   // 2097152
    const long long TT = (long long)SEQ * SEQ;   // 4194304

    // Phase 0: convert all inputs to half (main stream)
    cvt_f2h_all<<<2464, 256>>>((const float4*)X,  (uint4*)xh,
                               (const float4*)Wq, (uint4*)Wqh,
                               (const float4*)Wk, (uint4*)Wkh,
                               (const float4*)Wv, (uint4*)Wvh);
    cudaEventRecord(evCvt, 0);

    // Fork on s1: beta GEMVs, then V projection (reads xh/Wvh, writes g_v)
    cudaStreamWaitEvent(s1, evCvt, 0);
    gemv_wkbq<<<128, 256, 0, s1>>>(Wk, bq, bvec);
    gemv_beta<<<2048, 256, 0, s1>>>(xh, bvec, beta);
    cudaEventRecord(evBeta, s1);
    {
        dim3 grid(DIM / BN, MTOT / BM, 1);  // (8, 128, 1)
        gemm_fp16<false, true, true><<<grid, 256, SMEM_BYTES, s1>>>(
            xh, Wvh, bv, v, DIM, DIM, DIM, DIM, 0, 0, 0, 1.0f);
    }
    cudaEventRecord(evV, s1);

    // Main: M = Wq @ Wk^T (half out)
    {
        dim3 grid(DIM / BN, DIM / BM, 1);   // (8, 8, 1)
        gemm_fp16<true, true, false><<<grid, 256, SMEM_BYTES>>>(
            Wqh, Wkh, nullptr, mh, DIM, DIM, DIM, DIM, 0, 0, 0, 1.0f);
    }

    // Main: XM = X @ M (half out)
    {
        dim3 grid(DIM / BN, MTOT / BM, 1);  // (8, 128, 1)
        gemm_fp16<false, true, false><<<grid, 256, SMEM_BYTES>>>(
            xh, mh, nullptr, xm, DIM, DIM, DIM, DIM, 0, 0, 0, 1.0f);
    }

    // Main: scores = (XM) @ X^T / 32 + beta_j (half out, batched)
    cudaStreamWaitEvent(0, evBeta, 0);
    {
        dim3 grid(SEQ / BN, SEQ / BM, BATCH);  // (16, 16, 8)
        gemm_fp16<true, true, false><<<grid, 256, SMEM_BYTES>>>(
            xm, xh, beta, Sh, DIM, DIM, DIM, SEQ, TD, TD, TT, 0.03125f,
            nullptr, nullptr, nullptr, nullptr, nullptr, nullptr,
            (long long)SEQ);
    }

    // Softmax on half scores, in place
    softmax2048h<<<MTOT, 256>>>(Sh);

    // Join: PV needs V
    cudaStreamWaitEvent(0, evV, 0);

    // out = P @ V (fp32 out)
    {
        dim3 grid(DIM / BN, SEQ / BM, BATCH);  // (8, 16, 8)
        gemm_fp16<false, false, false><<<grid, 256, SMEM_BYTES>>>(
            Sh, v, nullptr, out, SEQ, SEQ, DIM, DIM, TT, TD, TD, 1.0f);
    }
}

// round 15
// speedup vs baseline: 1.9694x; 1.0141x over previous
#include <cuda_runtime.h>
#include <cstdint>
#include <cuda_fp16.h>
#include <mma.h>

using namespace nvcuda;

// Problem constants
#define BATCH 8
#define SEQ   2048
#define DIM   1024
#define MTOT  (BATCH * SEQ)        // 16384

// GEMM tiling: CTA 128x128, warp 64x32, K-chunk 64, double-buffered cp.async
#define BM 128
#define BN 128
#define BK 64
#define AKP 72                       // A row stride (halves) = 144 B
#define BKP 72                       // B trans row stride
#define BNP 136                      // B non-trans row stride = 272 B
#define A_STAGE 9216                 // 128*72 halves
#define B_STAGE 9216                 // max(128*72, 64*136) halves
#define STAGE_HALVES (A_STAGE + B_STAGE)
#define SMEM_BYTES (2 * STAGE_HALVES * 2)   // 73728 B (2 CTAs/SM = 144KB)

// Scratch (__device__ globals; allocation-free rule)
__device__ __half g_x[(long long)MTOT * DIM];   // 32 MB  Xh
__device__ __half g_w[3LL * DIM * DIM];         //  6 MB  Wq,Wk,Wv half
__device__ __half g_m[(long long)DIM * DIM];    //  2 MB  M = Wq Wk^T (half)
__device__ __half g_xm[(long long)MTOT * DIM];  // 32 MB  XM (half)
__device__ __half g_v[(long long)MTOT * DIM];   // 32 MB  V
__device__ __half g_s[(long long)MTOT * SEQ];   // 64 MB  half scores / P
__device__ float  g_bvec[DIM];                  // Wk@bq / 32
__device__ float  g_beta[MTOT];                 // X @ bvec (pre-scaled by 1/32)

__device__ __forceinline__ void cp16(void* smem, const void* gmem) {
    unsigned s = (unsigned)__cvta_generic_to_shared(smem);
    asm volatile("cp.async.cg.shared.global [%0], [%1], 16;\n" :: "r"(s), "l"(gmem));
}
#define CP_COMMIT() asm volatile("cp.async.commit_group;\n")

// ---------------------------------------------------------------------------
// FP16 WMMA GEMM (fp32 accumulate), double-buffered cp.async, 64x32 warp tiles.
//   C[M,N] = scale * (A[M,K] @ B(^T)) (+ bias, HALF_OUT only)
//   QKV3: blockIdx.z selects (B, bias, C) among up to 3 sets; A shared.
//   sBias: per-z element offset into bias (batched column bias, e.g. beta).
// ---------------------------------------------------------------------------
template <bool TRANSB, bool HALF_OUT, bool QKV3>
__global__ __launch_bounds__(256, 2)
void gemm_fp16(const __half* __restrict__ Ab, const __half* __restrict__ Bb,
               const float* __restrict__ bias, void* __restrict__ Cb,
               int K, int lda, int ldb, int ldc,
               long long sA, long long sB, long long sC, float scale,
               const __half* __restrict__ Bb1 = nullptr,
               const __half* __restrict__ Bb2 = nullptr,
               const float* __restrict__ bias1 = nullptr,
               const float* __restrict__ bias2 = nullptr,
               void* __restrict__ Cb1 = nullptr,
               void* __restrict__ Cb2 = nullptr,
               long long sBias = 0)
{
    extern __shared__ __half sh[];
    __shared__ float epi[8][16 * 20];
    __shared__ float biasS[BN];

    const __half* A = Ab;
    const __half* B = Bb;
    const float*  bi = bias;
    void*         Cv = Cb;

    if constexpr (QKV3) {
        if (blockIdx.z == 1)      { B = Bb1; bi = bias1; Cv = Cb1; }
        else if (blockIdx.z == 2) { B = Bb2; bi = bias2; Cv = Cb2; }
    } else {
        A += (long long)blockIdx.z * sA;
        B += (long long)blockIdx.z * sB;
        if (bi) bi += (long long)blockIdx.z * sBias;
    }

    const int m0 = blockIdx.y * BM;
    const int n0 = blockIdx.x * BN;
    const int t  = threadIdx.x;
    const int warp = t >> 5;
    const int lid  = t & 31;
    const int wm = warp >> 2;   // 0..1 (64-row slab)
    const int wn = warp & 3;    // 0..3 (32-col slab)

    if (HALF_OUT && t < BN) biasS[t] = bi ? bi[n0 + t] : 0.0f;

    wmma::fragment<wmma::accumulator, 16, 16, 16, float> acc[4][2];
    #pragma unroll
    for (int mi = 0; mi < 4; mi++)
        #pragma unroll
        for (int nj = 0; nj < 2; nj++)
            wmma::fill_fragment(acc[mi][nj], 0.0f);

    // Stage one K=64 chunk into buffer slot b (0/1)
    auto stage = [&](int chunk, int b) {
        const int k0 = chunk * BK;
        __half* Ad = sh + b * STAGE_HALVES;
        __half* Bd = Ad + A_STAGE;
        #pragma unroll
        for (int j = 0; j < 4; j++) {              // A: 128x64 = 1024 cp16
            int idx = t + 256 * j;
            int r  = idx >> 3;                     // 0..127
            int c8 = (idx & 7) << 3;               // 0..56
            cp16(&Ad[r * AKP + c8], &A[(long long)(m0 + r) * lda + k0 + c8]);
        }
        if (TRANSB) {
            #pragma unroll
            for (int j = 0; j < 4; j++) {          // B: 128x64 = 1024 cp16
                int idx = t + 256 * j;
                int r  = idx >> 3;
                int c8 = (idx & 7) << 3;
                cp16(&Bd[r * BKP + c8], &B[(long long)(n0 + r) * ldb + k0 + c8]);
            }
        } else {
            #pragma unroll
            for (int j = 0; j < 4; j++) {          // B: 64x128 = 1024 cp16
                int idx = t + 256 * j;
                int r  = idx >> 4;                 // 0..63
                int c8 = (idx & 15) << 3;          // 0..120
                cp16(&Bd[r * BNP + c8], &B[(long long)(k0 + r) * ldb + n0 + c8]);
            }
        }
        CP_COMMIT();
    };

    const int nchunk = K / BK;
    stage(0, 0);

    int cur = 0;
    for (int i = 0; i < nchunk; i++) {
        if (i + 1 < nchunk) {
            stage(i + 1, cur ^ 1);
            asm volatile("cp.async.wait_group 1;\n");
        } else {
            asm volatile("cp.async.wait_group 0;\n");
        }
        __syncthreads();

        const __half* Ac = sh + cur * STAGE_HALVES;
        const __half* Bc = Ac + A_STAGE;

        #pragma unroll
        for (int kk = 0; kk < BK; kk += 16) {
            wmma::fragment<wmma::matrix_a, 16, 16, 16, __half, wmma::row_major> af[4];
            #pragma unroll
            for (int mi = 0; mi < 4; mi++)
                wmma::load_matrix_sync(af[mi], &Ac[(wm * 64 + mi * 16) * AKP + kk], AKP);

            #pragma unroll
            for (int nj = 0; nj < 2; nj++) {
                if constexpr (TRANSB) {
                    wmma::fragment<wmma::matrix_b, 16, 16, 16, __half,
                                   wmma::col_major> bf;
                    wmma::load_matrix_sync(bf, &Bc[(wn * 32 + nj * 16) * BKP + kk], BKP);
                    #pragma unroll
                    for (int mi = 0; mi < 4; mi++)
                        wmma::mma_sync(acc[mi][nj], af[mi], bf, acc[mi][nj]);
                } else {
                    wmma::fragment<wmma::matrix_b, 16, 16, 16, __half,
                                   wmma::row_major> bf;
                    wmma::load_matrix_sync(bf, &Bc[kk * BNP + wn * 32 + nj * 16], BNP);
                    #pragma unroll
                    for (int mi = 0; mi < 4; mi++)
                        wmma::mma_sync(acc[mi][nj], af[mi], bf, acc[mi][nj]);
                }
            }
        }
        __syncthreads();
        cur ^= 1;
    }

    // Epilogue
    if constexpr (!HALF_OUT) {
        float* C = (float*)Cv + (QKV3 ? 0LL : (long long)blockIdx.z * sC);
        #pragma unroll
        for (int mi = 0; mi < 4; mi++)
            #pragma unroll
            for (int nj = 0; nj < 2; nj++) {
                if (scale != 1.0f) {
                    #pragma unroll
                    for (int e = 0; e < acc[mi][nj].num_elements; e++)
                        acc[mi][nj].x[e] *= scale;
                }
                wmma::store_matrix_sync(
                    &C[(long long)(m0 + wm * 64 + mi * 16) * ldc + n0 + wn * 32 + nj * 16],
                    acc[mi][nj], ldc, wmma::mem_row_major);
            }
    } else {
        __half* C = (__half*)Cv + (QKV3 ? 0LL : (long long)blockIdx.z * sC);
        float* ep = epi[warp];
        const int r  = lid >> 1;          // 0..15
        const int ch = (lid & 1) * 8;     // 0 or 8
        #pragma unroll
        for (int mi = 0; mi < 4; mi++)
            #pragma unroll
            for (int nj = 0; nj < 2; nj++) {
                wmma::store_matrix_sync(ep, acc[mi][nj], 20, wmma::mem_row_major);
                __syncwarp();
                const int colb = wn * 32 + nj * 16 + ch;
                __half h[8];
                #pragma unroll
                for (int i = 0; i < 8; i++)
                    h[i] = __float2half_rn(ep[r * 20 + ch + i] * scale + biasS[colb + i]);
                *(uint4*)&C[(long long)(m0 + wm * 64 + mi * 16 + r) * ldc + n0 + colb] =
                    *(uint4*)h;
                __syncwarp();
            }
    }
}

// ---------------------------------------------------------------------------
// Fused float->half conversion of X, Wq, Wk, Wv in ONE launch.
// ---------------------------------------------------------------------------
__global__ __launch_bounds__(256)
void cvt_f2h_all(const float4* __restrict__ X,  uint4* __restrict__ Xo,
                 const float4* __restrict__ W0, uint4* __restrict__ W0o,
                 const float4* __restrict__ W1, uint4* __restrict__ W1o,
                 const float4* __restrict__ W2, uint4* __restrict__ W2o)
{
    const int NX = MTOT * DIM / 8;     // 2097152
    const int NW = DIM * DIM / 8;      // 131072
    const int total = NX + 3 * NW;
    for (int i = blockIdx.x * blockDim.x + threadIdx.x; i < total;
         i += gridDim.x * blockDim.x) {
        const float4* in; uint4* out; int j;
        if (i < NX)                { in = X;  out = Xo;  j = i; }
        else if (i < NX + NW)      { in = W0; out = W0o; j = i - NX; }
        else if (i < NX + 2 * NW)  { in = W1; out = W1o; j = i - NX - NW; }
        else                       { in = W2; out = W2o; j = i - NX - 2 * NW; }
        float4 a = in[j * 2], b = in[j * 2 + 1];
        __half h[8];
        h[0] = __float2half_rn(a.x); h[1] = __float2half_rn(a.y);
        h[2] = __float2half_rn(a.z); h[3] = __float2half_rn(a.w);
        h[4] = __float2half_rn(b.x); h[5] = __float2half_rn(b.y);
        h[6] = __float2half_rn(b.z); h[7] = __float2half_rn(b.w);
        out[j] = *(uint4*)h;
    }
}

// ---------------------------------------------------------------------------
// bvec = (Wk @ bq) / 32  — one warp per row of Wk (fp32 input)
// ---------------------------------------------------------------------------
__global__ __launch_bounds__(256)
void gemv_wkbq(const float* __restrict__ Wk, const float* __restrict__ bq,
               float* __restrict__ bvec)
{
    int row  = (blockIdx.x * blockDim.x + threadIdx.x) >> 5;
    int lane = threadIdx.x & 31;
    if (row >= DIM) return;
    const float* w = Wk + (long long)row * DIM;
    float acc = 0.0f;
    for (int d = lane; d < DIM; d += 32) acc += w[d] * bq[d];
    #pragma unroll
    for (int o = 16; o > 0; o >>= 1) acc += __shfl_xor_sync(0xffffffffu, acc, o);
    if (lane == 0) bvec[row] = acc * 0.03125f;
}

// ---------------------------------------------------------------------------
// beta[j] = Xh[j,:] . bvec  — one warp per row of Xh (pre-scaled by 1/32)
// ---------------------------------------------------------------------------
__global__ __launch_bounds__(256)
void gemv_beta(const __half* __restrict__ Xh, const float* __restrict__ bvec,
               float* __restrict__ beta)
{
    int row  = (blockIdx.x * blockDim.x + threadIdx.x) >> 5;
    int lane = threadIdx.x & 31;
    if (row >= MTOT) return;
    const __half2* x = (const __half2*)(Xh + (long long)row * DIM);
    float acc = 0.0f;
    for (int d = lane; d < DIM / 2; d += 32) {
        float2 xv = __half22float2(x[d]);
        acc += xv.x * bvec[2 * d] + xv.y * bvec[2 * d + 1];
    }
    #pragma unroll
    for (int o = 16; o > 0; o >>= 1) acc += __shfl_xor_sync(0xffffffffu, acc, o);
    if (lane == 0) beta[row] = acc;
}

// ---------------------------------------------------------------------------
// Row softmax over 2048 HALF scores, fp32 math, writes half in place.
// ---------------------------------------------------------------------------
__global__ __launch_bounds__(256)
void softmax2048h(__half* __restrict__ S)
{
    __half* p = S + (long long)blockIdx.x * SEQ;
    const int t = threadIdx.x;

    uint4 raw = *(const uint4*)&p[t * 8];
    __half* hp = (__half*)&raw;
    float x[8];
    #pragma unroll
    for (int i = 0; i < 8; i++) x[i] = __half2float(hp[i]);

    float m = x[0];
    #pragma unroll
    for (int i = 1; i < 8; i++) m = fmaxf(m, x[i]);
    #pragma unroll
    for (int o = 16; o > 0; o >>= 1)
        m = fmaxf(m, __shfl_xor_sync(0xffffffffu, m, o));

    __shared__ float sm[8], ss[8];
    if ((t & 31) == 0) sm[t >> 5] = m;
    __syncthreads();
    m = fmaxf(fmaxf(fmaxf(sm[0], sm[1]), fmaxf(sm[2], sm[3])),
              fmaxf(fmaxf(sm[4], sm[5]), fmaxf(sm[6], sm[7])));

    float s = 0.0f;
    #pragma unroll
    for (int i = 0; i < 8; i++) { x[i] = __expf(x[i] - m); s += x[i]; }
    #pragma unroll
    for (int o = 16; o > 0; o >>= 1)
        s += __shfl_xor_sync(0xffffffffu, s, o);
    if ((t & 31) == 0) ss[t >> 5] = s;
    __syncthreads();
    s = (ss[0] + ss[1] + ss[2] + ss[3]) + (ss[4] + ss[5] + ss[6] + ss[7]);

    float inv = 1.0f / s;
    #pragma unroll
    for (int i = 0; i < 8; i++) hp[i] = __float2half_rn(x[i] * inv);
    *(uint4*)&p[t * 8] = raw;
}

// ---------------------------------------------------------------------------
extern "C" void kernel_launch(void* const* d_in, const int* in_sizes, int n_in,
                              void* d_out, int out_size)
{
    const float* X  = (const float*)d_in[0];
    const float* Wq = (const float*)d_in[1];
    const float* bq = (const float*)d_in[2];
    const float* Wk = (const float*)d_in[3];
    const float* bk = (const float*)d_in[4];
    const float* Wv = (const float*)d_in[5];
    const float* bv = (const float*)d_in[6];
    float* out = (float*)d_out;
    (void)bk;   // cancels in softmax (row-constant term)

    __half *xh, *wh, *mh, *xm, *v, *sh_;
    float *bvec, *beta;
    cudaGetSymbolAddress((void**)&xh, g_x);
    cudaGetSymbolAddress((void**)&wh, g_w);
    cudaGetSymbolAddress((void**)&mh, g_m);
    cudaGetSymbolAddress((void**)&xm, g_xm);
    cudaGetSymbolAddress((void**)&v, g_v);
    cudaGetSymbolAddress((void**)&sh_, g_s);
    cudaGetSymbolAddress((void**)&bvec, g_bvec);
    cudaGetSymbolAddress((void**)&beta, g_beta);

    __half* Wqh = wh;
    __half* Wkh = wh + (long long)DIM * DIM;
    __half* Wvh = wh + 2LL * DIM * DIM;
    __half* Sh  = sh_;

    // One-time host-side resources (no device memory involved).
    static cudaStream_t s1 = nullptr;
    static cudaEvent_t evCvt = nullptr, evBeta = nullptr, evXM = nullptr,
                       evV = nullptr, evEnd = nullptr;
    if (s1 == nullptr) {
        cudaStreamCreateWithFlags(&s1, cudaStreamNonBlocking);
        cudaEventCreateWithFlags(&evCvt,  cudaEventDisableTiming);
        cudaEventCreateWithFlags(&evBeta, cudaEventDisableTiming);
        cudaEventCreateWithFlags(&evXM,   cudaEventDisableTiming);
        cudaEventCreateWithFlags(&evV,    cudaEventDisableTiming);
        cudaEventCreateWithFlags(&evEnd,  cudaEventDisableTiming);
    }

    cudaFuncSetAttribute(gemm_fp16<false, true, true>,
                         cudaFuncAttributeMaxDynamicSharedMemorySize, SMEM_BYTES);
    cudaFuncSetAttribute(gemm_fp16<true, true, false>,
                         cudaFuncAttributeMaxDynamicSharedMemorySize, SMEM_BYTES);
    cudaFuncSetAttribute(gemm_fp16<false, true, false>,
                         cudaFuncAttributeMaxDynamicSharedMemorySize, SMEM_BYTES);
    cudaFuncSetAttribute(gemm_fp16<false, false, false>,
                         cudaFuncAttributeMaxDynamicSharedMemorySize, SMEM_BYTES);

    const long long TD = (long long)SEQ * DIM;   // 2097152
    const long long TT = (long long)SEQ * SEQ;   // 4194304
    const int HB = BATCH / 2;                    // 4 batches per half

    // Phase 0: convert all inputs to half (main stream)
    cvt_f2h_all<<<2464, 256>>>((const float4*)X,  (uint4*)xh,
                               (const float4*)Wq, (uint4*)Wqh,
                               (const float4*)Wk, (uint4*)Wkh,
                               (const float4*)Wv, (uint4*)Wvh);
    cudaEventRecord(evCvt, 0);

    // Fork on s1: beta GEMVs, then V projection
    cudaStreamWaitEvent(s1, evCvt, 0);
    gemv_wkbq<<<128, 256, 0, s1>>>(Wk, bq, bvec);
    gemv_beta<<<2048, 256, 0, s1>>>(xh, bvec, beta);
    cudaEventRecord(evBeta, s1);
    {
        dim3 grid(DIM / BN, MTOT / BM, 1);  // (8, 128, 1)
        gemm_fp16<false, true, true><<<grid, 256, SMEM_BYTES, s1>>>(
            xh, Wvh, bv, v, DIM, DIM, DIM, DIM, 0, 0, 0, 1.0f);
    }
    cudaEventRecord(evV, s1);

    // Main: M = Wq @ Wk^T, then XM = X @ M
    {
        dim3 grid(DIM / BN, DIM / BM, 1);   // (8, 8, 1)
        gemm_fp16<true, true, false><<<grid, 256, SMEM_BYTES>>>(
            Wqh, Wkh, nullptr, mh, DIM, DIM, DIM, DIM, 0, 0, 0, 1.0f);
    }
    {
        dim3 grid(DIM / BN, MTOT / BM, 1);  // (8, 128, 1)
        gemm_fp16<false, true, false><<<grid, 256, SMEM_BYTES>>>(
            xh, mh, nullptr, xm, DIM, DIM, DIM, DIM, 0, 0, 0, 1.0f);
    }
    cudaEventRecord(evXM, 0);

    // ---- Batch half A (b=0..3) on MAIN stream ----
    cudaStreamWaitEvent(0, evBeta, 0);
    {
        dim3 grid(SEQ / BN, SEQ / BM, HB);  // (16, 16, 4)
        gemm_fp16<true, true, false><<<grid, 256, SMEM_BYTES>>>(
            xm, xh, beta, Sh, DIM, DIM, DIM, SEQ, TD, TD, TT, 0.03125f,
            nullptr, nullptr, nullptr, nullptr, nullptr, nullptr,
            (long long)SEQ);
    }
    softmax2048h<<<HB * SEQ, 256>>>(Sh);
    cudaStreamWaitEvent(0, evV, 0);
    {
        dim3 grid(DIM / BN, SEQ / BM, HB);  // (8, 16, 4)
        gemm_fp16<false, false, false><<<grid, 256, SMEM_BYTES>>>(
            Sh, v, nullptr, out, SEQ, SEQ, DIM, DIM, TT, TD, TD, 1.0f);
    }

    // ---- Batch half B (b=4..7) on s1 (overlaps half A's softmax/PV) ----
    cudaStreamWaitEvent(s1, evXM, 0);
    {
        dim3 grid(SEQ / BN, SEQ / BM, HB);
        gemm_fp16<true, true, false><<<grid, 256, SMEM_BYTES, s1>>>(
            xm + (long long)HB * TD, xh + (long long)HB * TD,
            beta + (long long)HB * SEQ, Sh + (long long)HB * TT,
            DIM, DIM, DIM, SEQ, TD, TD, TT, 0.03125f,
            nullptr, nullptr, nullptr, nullptr, nullptr, nullptr,
            (long long)SEQ);
    }
    softmax2048h<<<HB * SEQ, 256, 0, s1>>>(Sh + (long long)HB * TT);
    {
        dim3 grid(DIM / BN, SEQ / BM, HB);
        gemm_fp16<false, false, false><<<grid, 256, SMEM_BYTES, s1>>>(
            Sh + (long long)HB * TT, v + (long long)HB * TD, nullptr,
            out + (long long)HB * TD, SEQ, SEQ, DIM, DIM, TT, TD, TD, 1.0f);
    }
    cudaEventRecord(evEnd, s1);

    // Join s1 back into the capture-origin stream
    cudaStreamWaitEvent(0, evEnd, 0);
}